// round 2
// baseline (speedup 1.0000x reference)
#include <cuda_runtime.h>
#include <math.h>

// ---------------------------------------------------------------------------
// PairwiseInteractionHead: B=4, LL=LP=256, D=256, H=128, TOPK=100
// Factorization: z1[h] = A1[i,h] + B1[j,h] + sum_k Wc[h,k] l[i,k] p[j,k]
//                               + sum_k Wd[h,k] |l[i,k]-p[j,k]|
// Round 2: packed fma.rn.f32x2 in both pair-GEMM inner loops (2x fp32 FMA).
// ---------------------------------------------------------------------------

#define NB 4
#define LSEQ 256
#define DDIM 256
#define HDIM 128
#define NPAIR_B 65536
#define TOPK_K 100

__device__ float g_lproj[NB * LSEQ * DDIM];
__device__ float g_pproj[NB * LSEQ * DDIM];
__device__ float g_A1[NB * LSEQ * HDIM];
__device__ float g_B1[NB * LSEQ * HDIM];
__device__ int   g_lmask[NB * LSEQ];
__device__ int   g_pmask[NB * LSEQ];
__device__ int   g_flags[2];

__device__ __forceinline__ float gelu_f(float x) {
    return 0.5f * x * (1.0f + erff(x * 0.70710678118654752440f));
}

__device__ __forceinline__ unsigned long long fma2(
    unsigned long long a, unsigned long long b, unsigned long long c) {
    unsigned long long d;
    asm("fma.rn.f32x2 %0, %1, %2, %3;" : "=l"(d) : "l"(a), "l"(b), "l"(c));
    return d;
}
__device__ __forceinline__ unsigned long long pack2(float lo, float hi) {
    unsigned long long d;
    asm("mov.b64 %0, {%1, %2};" : "=l"(d) : "f"(lo), "f"(hi));
    return d;
}
__device__ __forceinline__ void unpack2(float& lo, float& hi, unsigned long long v) {
    asm("mov.b64 {%0, %1}, %2;" : "=f"(lo), "=f"(hi) : "l"(v));
}

// ---------------------------------------------------------------------------
// Pad-dtype detection (bool may arrive as uint8/int32/float32)
// ---------------------------------------------------------------------------
__global__ void detect_kernel(const unsigned char* lp, const unsigned char* pp) {
    __shared__ int s_nonbin, s_oddnz, s_anynz;
    const unsigned char* p = blockIdx.x ? pp : lp;
    if (threadIdx.x == 0) { s_nonbin = 0; s_oddnz = 0; s_anynz = 0; }
    __syncthreads();
    int nonbin = 0, oddnz = 0, anynz = 0;
    for (int i = threadIdx.x; i < 1024; i += blockDim.x) {
        unsigned v = p[i];
        if (v) { anynz = 1; if (v > 1u) nonbin = 1; if (i & 3) oddnz = 1; }
    }
    if (nonbin) atomicOr(&s_nonbin, 1);
    if (oddnz)  atomicOr(&s_oddnz, 1);
    if (anynz)  atomicOr(&s_anynz, 1);
    __syncthreads();
    if (threadIdx.x == 0) {
        int f;
        if (!s_anynz) f = 0;
        else if (s_nonbin) f = 2;
        else if (s_oddnz) f = 1;
        else f = 3;
        g_flags[blockIdx.x] = f;
    }
}

__global__ void mask_kernel(const void* lp, const void* pp) {
    int buf = blockIdx.x;
    const void* p = buf ? pp : lp;
    int f = g_flags[buf];
    int i = threadIdx.x;
    int m;
    if (f == 0) m = 0;
    else if (f == 1) m = (((const unsigned char*)p)[i] != 0);
    else if (f == 2) m = (((const float*)p)[i] != 0.0f);
    else m = (((const int*)p)[i] != 0);
    (buf ? g_pmask : g_lmask)[i] = m;
}

// ---------------------------------------------------------------------------
// Projection GEMM (l/p): M=2048 N=256 K=256
// ---------------------------------------------------------------------------
__global__ __launch_bounds__(256) void proj_kernel(
    const float* __restrict__ ltok, const float* __restrict__ ptok,
    const float* __restrict__ Wl, const float* __restrict__ bl,
    const float* __restrict__ Wp, const float* __restrict__ bp)
{
    __shared__ float As[16][68];
    __shared__ float Bs[16][68];
    const int n0 = blockIdx.x * 64;
    const int m0 = blockIdx.y * 64;
    const bool isP = (m0 >= 1024);
    const float* in   = isP ? ptok : ltok;
    const float* W    = isP ? Wp : Wl;
    const float* bias = isP ? bp : bl;
    const int mb = isP ? (m0 - 1024) : m0;
    float* outp = isP ? g_pproj : g_lproj;
    const int tid = threadIdx.x;
    const int tx = tid & 15, ty = tid >> 4;
    const int lr = tid >> 2, lc = (tid & 3) * 4;
    float acc[4][4] = {};
    for (int kt = 0; kt < 256; kt += 16) {
        float4 a4 = *(const float4*)&in[(mb + lr) * 256 + kt + lc];
        float4 b4 = *(const float4*)&W[(n0 + lr) * 256 + kt + lc];
        As[lc + 0][lr] = a4.x; As[lc + 1][lr] = a4.y; As[lc + 2][lr] = a4.z; As[lc + 3][lr] = a4.w;
        Bs[lc + 0][lr] = b4.x; Bs[lc + 1][lr] = b4.y; Bs[lc + 2][lr] = b4.z; Bs[lc + 3][lr] = b4.w;
        __syncthreads();
#pragma unroll
        for (int e = 0; e < 16; e++) {
            float4 av = *(const float4*)&As[e][ty * 4];
            float4 bv = *(const float4*)&Bs[e][tx * 4];
            acc[0][0] += av.x * bv.x; acc[0][1] += av.x * bv.y; acc[0][2] += av.x * bv.z; acc[0][3] += av.x * bv.w;
            acc[1][0] += av.y * bv.x; acc[1][1] += av.y * bv.y; acc[1][2] += av.y * bv.z; acc[1][3] += av.y * bv.w;
            acc[2][0] += av.z * bv.x; acc[2][1] += av.z * bv.y; acc[2][2] += av.z * bv.z; acc[2][3] += av.z * bv.w;
            acc[3][0] += av.w * bv.x; acc[3][1] += av.w * bv.y; acc[3][2] += av.w * bv.z; acc[3][3] += av.w * bv.w;
        }
        __syncthreads();
    }
#pragma unroll
    for (int ii = 0; ii < 4; ii++) {
#pragma unroll
        for (int jj = 0; jj < 4; jj++) {
            int n = n0 + tx * 4 + jj;
            outp[(mb + ty * 4 + ii) * 256 + n] = acc[ii][jj] + bias[n];
        }
    }
}

// ---------------------------------------------------------------------------
// A1 = l_proj @ W1[:,0:256]^T + b1 ; B1 = p_proj @ W1[:,256:512]^T
// ---------------------------------------------------------------------------
__global__ __launch_bounds__(256) void a1b1_kernel(
    const float* __restrict__ W1, const float* __restrict__ b1)
{
    __shared__ float As[16][68];
    __shared__ float Bs[16][68];
    const int n0 = blockIdx.x * 64;
    const int m0 = blockIdx.y * 64;
    const bool isP = (m0 >= 1024);
    const float* in = isP ? g_pproj : g_lproj;
    const int mb = isP ? (m0 - 1024) : m0;
    const int colOff = isP ? 256 : 0;
    float* outp = isP ? g_B1 : g_A1;
    const int tid = threadIdx.x;
    const int tx = tid & 15, ty = tid >> 4;
    const int lr = tid >> 2, lc = (tid & 3) * 4;
    float acc[4][4] = {};
    for (int kt = 0; kt < 256; kt += 16) {
        float4 a4 = *(const float4*)&in[(mb + lr) * 256 + kt + lc];
        float4 b4 = *(const float4*)&W1[(n0 + lr) * 1024 + colOff + kt + lc];
        As[lc + 0][lr] = a4.x; As[lc + 1][lr] = a4.y; As[lc + 2][lr] = a4.z; As[lc + 3][lr] = a4.w;
        Bs[lc + 0][lr] = b4.x; Bs[lc + 1][lr] = b4.y; Bs[lc + 2][lr] = b4.z; Bs[lc + 3][lr] = b4.w;
        __syncthreads();
#pragma unroll
        for (int e = 0; e < 16; e++) {
            float4 av = *(const float4*)&As[e][ty * 4];
            float4 bv = *(const float4*)&Bs[e][tx * 4];
            acc[0][0] += av.x * bv.x; acc[0][1] += av.x * bv.y; acc[0][2] += av.x * bv.z; acc[0][3] += av.x * bv.w;
            acc[1][0] += av.y * bv.x; acc[1][1] += av.y * bv.y; acc[1][2] += av.y * bv.z; acc[1][3] += av.y * bv.w;
            acc[2][0] += av.z * bv.x; acc[2][1] += av.z * bv.y; acc[2][2] += av.z * bv.z; acc[2][3] += av.z * bv.w;
            acc[3][0] += av.w * bv.x; acc[3][1] += av.w * bv.y; acc[3][2] += av.w * bv.z; acc[3][3] += av.w * bv.w;
        }
        __syncthreads();
    }
#pragma unroll
    for (int ii = 0; ii < 4; ii++) {
#pragma unroll
        for (int jj = 0; jj < 4; jj++) {
            int n = n0 + tx * 4 + jj;
            float bv = isP ? 0.0f : b1[n];
            outp[(mb + ty * 4 + ii) * 128 + n] = acc[ii][jj] + bv;
        }
    }
}

// ---------------------------------------------------------------------------
// Main pair kernel with f32x2 packed FMA.
// Block = (b, 16 i, 16 j) = 256 pairs, 512 threads, micro-tile 8p x 8h.
// smem phase 1 (floats):
//   Ls[16][260] @0, Ps[16][260] @4160, Xs[32][256] @8320,
//   Wd (ull[32][132], duplicated {w,w}) @float 16512, A1s[16][132] @24960,
//   B1s[16][132] @27072  (ends 29184 floats = 116736 B)
// phase 2 (aliased):  Yt[128][264] @0 (135168 B), W2s[128][136] @33792 floats
// total dynamic smem 204800 B.
// ---------------------------------------------------------------------------
__global__ __launch_bounds__(512, 1) void pair_kernel(
    const float* __restrict__ W1, const float* __restrict__ W2,
    const float* __restrict__ W3, const float* __restrict__ b2g,
    const float* __restrict__ b3, float* __restrict__ out)
{
    extern __shared__ float sm[];
    float* Ls  = sm;
    float* Ps  = sm + 16 * 260;
    float* Xs  = sm + 2 * 16 * 260;
    unsigned long long* Wd = (unsigned long long*)(sm + 16512);  // [32][132] ull
    float* A1s = sm + 24960;
    float* B1s = sm + 27072;
    float* Yt  = sm;                       // phase 2
    float* W2s = sm + 128 * 264;           // phase 2 (disjoint from phase-1 region)

    const int tid = threadIdx.x;
    const int b  = blockIdx.z;
    const int it = blockIdx.y * 16;
    const int jt = blockIdx.x * 16;
    const int pg = tid >> 4;
    const int hg = tid & 15;
    const int p0 = pg * 8;
    const int h0 = hg * 8;
    const int my_i = p0 >> 4;
    const int j0 = p0 & 15;

    // ---- initial loads ----
    {
        const float* lsrc = g_lproj + (b * 256 + it) * 256;
        const float* psrc = g_pproj + (b * 256 + jt) * 256;
#pragma unroll
        for (int q = 0; q < 2; q++) {
            int f4 = q * 512 + tid;
            int r = f4 >> 6;
            int c = (f4 & 63) * 4;
            *(float4*)&Ls[r * 260 + c] = *(const float4*)&lsrc[r * 256 + c];
            *(float4*)&Ps[r * 260 + c] = *(const float4*)&psrc[r * 256 + c];
        }
        const float* a1src = g_A1 + (b * 256 + it) * 128;
        const float* b1src = g_B1 + (b * 256 + jt) * 128;
        {
            int f4 = tid;
            int r = f4 >> 5;
            int c = (f4 & 31) * 4;
            *(float4*)&A1s[r * 132 + c] = *(const float4*)&a1src[r * 128 + c];
            *(float4*)&B1s[r * 132 + c] = *(const float4*)&b1src[r * 128 + c];
        }
#pragma unroll
        for (int q = 0; q < 8; q++) {
            int f4 = q * 512 + tid;
            int f = f4 * 4;
            int g = f >> 7, h = f & 127;
            float4 v = *(const float4*)&W2[f];
            W2s[(h + 0) * 136 + g] = v.x;
            W2s[(h + 1) * 136 + g] = v.y;
            W2s[(h + 2) * 136 + g] = v.z;
            W2s[(h + 3) * 136 + g] = v.w;
        }
    }
    __syncthreads();

    unsigned long long acc2[8][4];
#pragma unroll
    for (int a = 0; a < 8; a++)
#pragma unroll
        for (int q = 0; q < 4; q++) acc2[a][q] = 0ull;

    const int xk = tid >> 4;
    const int xi = tid & 15;

    for (int kc = 0; kc < 512; kc += 32) {
        // build Xs[xk][xi*16+u]
        {
            int kk = kc + xk;
            if (kk < 256) {
                float lv = Ls[xi * 260 + kk];
#pragma unroll
                for (int u = 0; u < 16; u++)
                    Xs[xk * 256 + xi * 16 + u] = lv * Ps[u * 260 + kk];
            } else {
                int kd = kk - 256;
                float lv = Ls[xi * 260 + kd];
#pragma unroll
                for (int u = 0; u < 16; u++)
                    Xs[xk * 256 + xi * 16 + u] = fabsf(lv - Ps[u * 260 + kd]);
            }
        }
        // load Wd[k][h] = {w,w}, w = W1[h*1024 + 512 + kc + k]
        {
            int h = tid >> 2;
            int k0 = (tid & 3) * 8;
            const float* src = W1 + h * 1024 + 512 + kc + k0;
            float4 v0 = *(const float4*)(src);
            float4 v1 = *(const float4*)(src + 4);
            Wd[(k0 + 0) * 132 + h] = pack2(v0.x, v0.x);
            Wd[(k0 + 1) * 132 + h] = pack2(v0.y, v0.y);
            Wd[(k0 + 2) * 132 + h] = pack2(v0.z, v0.z);
            Wd[(k0 + 3) * 132 + h] = pack2(v0.w, v0.w);
            Wd[(k0 + 4) * 132 + h] = pack2(v1.x, v1.x);
            Wd[(k0 + 5) * 132 + h] = pack2(v1.y, v1.y);
            Wd[(k0 + 6) * 132 + h] = pack2(v1.z, v1.z);
            Wd[(k0 + 7) * 132 + h] = pack2(v1.w, v1.w);
        }
        __syncthreads();
#pragma unroll 4
        for (int k = 0; k < 32; k++) {
            ulonglong2 x0 = *(const ulonglong2*)&Xs[k * 256 + p0];
            ulonglong2 x1 = *(const ulonglong2*)&Xs[k * 256 + p0 + 4];
            const unsigned long long* wr = &Wd[k * 132 + h0];
            ulonglong2 w0 = *(const ulonglong2*)(wr);
            ulonglong2 w1 = *(const ulonglong2*)(wr + 2);
            ulonglong2 w2v = *(const ulonglong2*)(wr + 4);
            ulonglong2 w3v = *(const ulonglong2*)(wr + 6);
            unsigned long long xv[4] = {x0.x, x0.y, x1.x, x1.y};
            unsigned long long wv[8] = {w0.x, w0.y, w1.x, w1.y, w2v.x, w2v.y, w3v.x, w3v.y};
#pragma unroll
            for (int a = 0; a < 8; a++)
#pragma unroll
                for (int q = 0; q < 4; q++)
                    acc2[a][q] = fma2(wv[a], xv[q], acc2[a][q]);
        }
        __syncthreads();
    }

    // epilogue1: + A1 + B1, gelu -> regs, then store to Yt
    float yreg[8][8];
#pragma unroll
    for (int a = 0; a < 8; a++) {
        float av = A1s[my_i * 132 + h0 + a];
#pragma unroll
        for (int q = 0; q < 4; q++) {
            float lo, hi;
            unpack2(lo, hi, acc2[a][q]);
            int p = 2 * q;
            float z0 = lo + av + B1s[(j0 + p) * 132 + h0 + a];
            float z1 = hi + av + B1s[(j0 + p + 1) * 132 + h0 + a];
            yreg[a][p] = gelu_f(z0);
            yreg[a][p + 1] = gelu_f(z1);
        }
    }
    __syncthreads();
#pragma unroll
    for (int a = 0; a < 8; a++)
#pragma unroll
        for (int p = 0; p < 8; p++)
            Yt[(h0 + a) * 264 + p0 + p] = yreg[a][p];
    __syncthreads();

    // GEMM2: out2[g][p] = sum_h Yt[h][p] * W2s[h][g]   (f32x2, packed along p)
#pragma unroll
    for (int a = 0; a < 8; a++)
#pragma unroll
        for (int q = 0; q < 4; q++) acc2[a][q] = 0ull;
#pragma unroll 4
    for (int h = 0; h < 128; h++) {
        ulonglong2 y0 = *(const ulonglong2*)&Yt[h * 264 + p0];
        ulonglong2 y1 = *(const ulonglong2*)&Yt[h * 264 + p0 + 4];
        float4 wa = *(const float4*)&W2s[h * 136 + h0];
        float4 wb = *(const float4*)&W2s[h * 136 + h0 + 4];
        unsigned long long xv[4] = {y0.x, y0.y, y1.x, y1.y};
        unsigned long long wv[8] = {
            pack2(wa.x, wa.x), pack2(wa.y, wa.y), pack2(wa.z, wa.z), pack2(wa.w, wa.w),
            pack2(wb.x, wb.x), pack2(wb.y, wb.y), pack2(wb.z, wb.z), pack2(wb.w, wb.w)};
#pragma unroll
        for (int a = 0; a < 8; a++)
#pragma unroll
            for (int q = 0; q < 4; q++)
                acc2[a][q] = fma2(wv[a], xv[q], acc2[a][q]);
    }

    // epilogue2: + b2, gelu, dot with w3
    float part[8];
#pragma unroll
    for (int p = 0; p < 8; p++) part[p] = 0.0f;
#pragma unroll
    for (int gg = 0; gg < 8; gg++) {
        float w3v = W3[h0 + gg];
        float b2v = b2g[h0 + gg];
#pragma unroll
        for (int q = 0; q < 4; q++) {
            float lo, hi;
            unpack2(lo, hi, acc2[gg][q]);
            part[2 * q]     += w3v * gelu_f(lo + b2v);
            part[2 * q + 1] += w3v * gelu_f(hi + b2v);
        }
    }
#pragma unroll
    for (int off = 8; off >= 1; off >>= 1) {
#pragma unroll
        for (int p = 0; p < 8; p++)
            part[p] += __shfl_xor_sync(0xFFFFFFFFu, part[p], off);
    }
    if (hg == 0) {
        const int gi = it + my_i;
        const int lpad = g_lmask[b * 256 + gi];
        const float b3v = b3[0];
#pragma unroll
        for (int p = 0; p < 8; p++) {
            int j = jt + j0 + p;
            float v = part[p] + b3v;
            if (isnan(v)) v = 0.0f;
            else if (isinf(v)) v = (v > 0.0f) ? 20.0f : -20.0f;
            if (lpad || g_pmask[b * 256 + j]) v = -20.0f;
            int idx = 4 + (b * 65536 + gi * 256 + j);
            out[idx] = v;
            out[idx + 262144] = 1.0f / (1.0f + expf(-v));
        }
    }
}

// ---------------------------------------------------------------------------
// Top-k (k=100) per batch via radix-select + tie-aware exp-sum.
// ---------------------------------------------------------------------------
__device__ __forceinline__ int wredsum_i(int v) {
#pragma unroll
    for (int o = 16; o; o >>= 1) v += __shfl_xor_sync(0xFFFFFFFFu, v, o);
    return v;
}
__device__ __forceinline__ float wredsum_f(float v) {
#pragma unroll
    for (int o = 16; o; o >>= 1) v += __shfl_xor_sync(0xFFFFFFFFu, v, o);
    return v;
}
__device__ __forceinline__ float wredmax_f(float v) {
#pragma unroll
    for (int o = 16; o; o >>= 1) v = fmaxf(v, __shfl_xor_sync(0xFFFFFFFFu, v, o));
    return v;
}

__global__ __launch_bounds__(1024) void topk_kernel(float* out) {
    const int b = blockIdx.x;
    const float* data = out + 4 + b * NPAIR_B;
    const int tid = threadIdx.x, lane = tid & 31, wid = tid >> 5;
    __shared__ float sf[32];
    __shared__ float sf2[32];
    __shared__ int si[32];
    __shared__ float s_M;
    __shared__ int s_tot;

    float mx = -1e30f;
    for (int i = tid; i < NPAIR_B; i += 1024) mx = fmaxf(mx, data[i]);
    mx = wredmax_f(mx);
    if (lane == 0) sf[wid] = mx;
    __syncthreads();
    if (wid == 0) {
        float v = sf[lane];
        v = wredmax_f(v);
        if (lane == 0) s_M = v;
    }
    __syncthreads();
    const float M = s_M;

    unsigned prefix = 0u;
    for (int bit = 31; bit >= 0; --bit) {
        unsigned test = prefix | (1u << bit);
        int c = 0;
        for (int i = tid; i < NPAIR_B; i += 1024) {
            unsigned u = __float_as_uint(data[i]);
            unsigned k = (u & 0x80000000u) ? ~u : (u | 0x80000000u);
            c += (k >= test) ? 1 : 0;
        }
        c = wredsum_i(c);
        if (lane == 0) si[wid] = c;
        __syncthreads();
        if (wid == 0) {
            int v = si[lane];
            v = wredsum_i(v);
            if (lane == 0) s_tot = v;
        }
        __syncthreads();
        if (s_tot >= TOPK_K) prefix = test;
        __syncthreads();
    }

    float s1 = 0.0f, s2 = 0.0f;
    int cg = 0;
    for (int i = tid; i < NPAIR_B; i += 1024) {
        float v = data[i];
        unsigned u = __float_as_uint(v);
        unsigned k = (u & 0x80000000u) ? ~u : (u | 0x80000000u);
        if (k > prefix) {
            float e = expf(v - M);
            s1 += e; s2 += e * v; cg++;
        }
    }
    s1 = wredsum_f(s1);
    s2 = wredsum_f(s2);
    cg = wredsum_i(cg);
    if (lane == 0) { sf[wid] = s1; sf2[wid] = s2; si[wid] = cg; }
    __syncthreads();
    if (tid == 0) {
        float S1 = 0.0f, S2 = 0.0f;
        int CG = 0;
        for (int w = 0; w < 32; w++) { S1 += sf[w]; S2 += sf2[w]; CG += si[w]; }
        unsigned u = (prefix & 0x80000000u) ? (prefix & 0x7FFFFFFFu) : ~prefix;
        float vT = __uint_as_float(u);
        int r = TOPK_K - CG;
        float e = expf(vT - M);
        S1 += (float)r * e;
        S2 += (float)r * e * vT;
        out[b] = S2 / S1;
    }
}

// ---------------------------------------------------------------------------
extern "C" void kernel_launch(void* const* d_in, const int* in_sizes, int n_in,
                              void* d_out, int out_size)
{
    const float* ltok = (const float*)d_in[0];
    const float* ptok = (const float*)d_in[1];
    const void*  lpad = d_in[2];
    const void*  ppad = d_in[3];
    const float* Wl = (const float*)d_in[4];
    const float* bl = (const float*)d_in[5];
    const float* Wp = (const float*)d_in[6];
    const float* bp = (const float*)d_in[7];
    const float* W1 = (const float*)d_in[8];
    const float* b1 = (const float*)d_in[9];
    const float* W2 = (const float*)d_in[10];
    const float* b2 = (const float*)d_in[11];
    const float* W3 = (const float*)d_in[12];
    const float* b3 = (const float*)d_in[13];
    float* out = (float*)d_out;

    detect_kernel<<<2, 256>>>((const unsigned char*)lpad, (const unsigned char*)ppad);
    mask_kernel<<<2, 1024>>>(lpad, ppad);
    proj_kernel<<<dim3(4, 32), 256>>>(ltok, ptok, Wl, bl, Wp, bp);
    a1b1_kernel<<<dim3(2, 32), 256>>>(W1, b1);

    cudaFuncSetAttribute(pair_kernel, cudaFuncAttributeMaxDynamicSharedMemorySize, 204800);
    pair_kernel<<<dim3(16, 16, 4), 512, 204800>>>(W1, W2, W3, b2, b3, out);

    topk_kernel<<<4, 1024>>>(out);
}

// round 3
// speedup vs baseline: 1.0008x; 1.0008x over previous
#include <cuda_runtime.h>
#include <math.h>

// ---------------------------------------------------------------------------
// PairwiseInteractionHead: B=4, LL=LP=256, D=256, H=128, TOPK=100
// Factorization: z1[h] = A1[i,h] + B1[j,h] + sum_k Wc[h,k] l[i,k] p[j,k]
//                               + sum_k Wd[h,k] |l[i,k]-p[j,k]|
// Round 2: packed fma.rn.f32x2 in both pair-GEMM inner loops (2x fp32 FMA).
// ---------------------------------------------------------------------------

#define NB 4
#define LSEQ 256
#define DDIM 256
#define HDIM 128
#define NPAIR_B 65536
#define TOPK_K 100

__device__ float g_lproj[NB * LSEQ * DDIM];
__device__ float g_pproj[NB * LSEQ * DDIM];
__device__ float g_A1[NB * LSEQ * HDIM];
__device__ float g_B1[NB * LSEQ * HDIM];
__device__ int   g_lmask[NB * LSEQ];
__device__ int   g_pmask[NB * LSEQ];
__device__ int   g_flags[2];

__device__ __forceinline__ float gelu_f(float x) {
    return 0.5f * x * (1.0f + erff(x * 0.70710678118654752440f));
}

__device__ __forceinline__ unsigned long long fma2(
    unsigned long long a, unsigned long long b, unsigned long long c) {
    unsigned long long d;
    asm("fma.rn.f32x2 %0, %1, %2, %3;" : "=l"(d) : "l"(a), "l"(b), "l"(c));
    return d;
}
__device__ __forceinline__ unsigned long long pack2(float lo, float hi) {
    unsigned long long d;
    asm("mov.b64 %0, {%1, %2};" : "=l"(d) : "f"(lo), "f"(hi));
    return d;
}
__device__ __forceinline__ void unpack2(float& lo, float& hi, unsigned long long v) {
    asm("mov.b64 {%0, %1}, %2;" : "=f"(lo), "=f"(hi) : "l"(v));
}

// ---------------------------------------------------------------------------
// Pad-dtype detection (bool may arrive as uint8/int32/float32)
// ---------------------------------------------------------------------------
__global__ void detect_kernel(const unsigned char* lp, const unsigned char* pp) {
    __shared__ int s_nonbin, s_oddnz, s_anynz;
    const unsigned char* p = blockIdx.x ? pp : lp;
    if (threadIdx.x == 0) { s_nonbin = 0; s_oddnz = 0; s_anynz = 0; }
    __syncthreads();
    int nonbin = 0, oddnz = 0, anynz = 0;
    for (int i = threadIdx.x; i < 1024; i += blockDim.x) {
        unsigned v = p[i];
        if (v) { anynz = 1; if (v > 1u) nonbin = 1; if (i & 3) oddnz = 1; }
    }
    if (nonbin) atomicOr(&s_nonbin, 1);
    if (oddnz)  atomicOr(&s_oddnz, 1);
    if (anynz)  atomicOr(&s_anynz, 1);
    __syncthreads();
    if (threadIdx.x == 0) {
        int f;
        if (!s_anynz) f = 0;
        else if (s_nonbin) f = 2;
        else if (s_oddnz) f = 1;
        else f = 3;
        g_flags[blockIdx.x] = f;
    }
}

__global__ void mask_kernel(const void* lp, const void* pp) {
    int buf = blockIdx.x;
    const void* p = buf ? pp : lp;
    int f = g_flags[buf];
    int i = threadIdx.x;
    int m;
    if (f == 0) m = 0;
    else if (f == 1) m = (((const unsigned char*)p)[i] != 0);
    else if (f == 2) m = (((const float*)p)[i] != 0.0f);
    else m = (((const int*)p)[i] != 0);
    (buf ? g_pmask : g_lmask)[i] = m;
}

// ---------------------------------------------------------------------------
// Projection GEMM (l/p): M=2048 N=256 K=256
// ---------------------------------------------------------------------------
__global__ __launch_bounds__(256) void proj_kernel(
    const float* __restrict__ ltok, const float* __restrict__ ptok,
    const float* __restrict__ Wl, const float* __restrict__ bl,
    const float* __restrict__ Wp, const float* __restrict__ bp)
{
    __shared__ float As[16][68];
    __shared__ float Bs[16][68];
    const int n0 = blockIdx.x * 64;
    const int m0 = blockIdx.y * 64;
    const bool isP = (m0 >= 1024);
    const float* in   = isP ? ptok : ltok;
    const float* W    = isP ? Wp : Wl;
    const float* bias = isP ? bp : bl;
    const int mb = isP ? (m0 - 1024) : m0;
    float* outp = isP ? g_pproj : g_lproj;
    const int tid = threadIdx.x;
    const int tx = tid & 15, ty = tid >> 4;
    const int lr = tid >> 2, lc = (tid & 3) * 4;
    float acc[4][4] = {};
    for (int kt = 0; kt < 256; kt += 16) {
        float4 a4 = *(const float4*)&in[(mb + lr) * 256 + kt + lc];
        float4 b4 = *(const float4*)&W[(n0 + lr) * 256 + kt + lc];
        As[lc + 0][lr] = a4.x; As[lc + 1][lr] = a4.y; As[lc + 2][lr] = a4.z; As[lc + 3][lr] = a4.w;
        Bs[lc + 0][lr] = b4.x; Bs[lc + 1][lr] = b4.y; Bs[lc + 2][lr] = b4.z; Bs[lc + 3][lr] = b4.w;
        __syncthreads();
#pragma unroll
        for (int e = 0; e < 16; e++) {
            float4 av = *(const float4*)&As[e][ty * 4];
            float4 bv = *(const float4*)&Bs[e][tx * 4];
            acc[0][0] += av.x * bv.x; acc[0][1] += av.x * bv.y; acc[0][2] += av.x * bv.z; acc[0][3] += av.x * bv.w;
            acc[1][0] += av.y * bv.x; acc[1][1] += av.y * bv.y; acc[1][2] += av.y * bv.z; acc[1][3] += av.y * bv.w;
            acc[2][0] += av.z * bv.x; acc[2][1] += av.z * bv.y; acc[2][2] += av.z * bv.z; acc[2][3] += av.z * bv.w;
            acc[3][0] += av.w * bv.x; acc[3][1] += av.w * bv.y; acc[3][2] += av.w * bv.z; acc[3][3] += av.w * bv.w;
        }
        __syncthreads();
    }
#pragma unroll
    for (int ii = 0; ii < 4; ii++) {
#pragma unroll
        for (int jj = 0; jj < 4; jj++) {
            int n = n0 + tx * 4 + jj;
            outp[(mb + ty * 4 + ii) * 256 + n] = acc[ii][jj] + bias[n];
        }
    }
}

// ---------------------------------------------------------------------------
// A1 = l_proj @ W1[:,0:256]^T + b1 ; B1 = p_proj @ W1[:,256:512]^T
// ---------------------------------------------------------------------------
__global__ __launch_bounds__(256) void a1b1_kernel(
    const float* __restrict__ W1, const float* __restrict__ b1)
{
    __shared__ float As[16][68];
    __shared__ float Bs[16][68];
    const int n0 = blockIdx.x * 64;
    const int m0 = blockIdx.y * 64;
    const bool isP = (m0 >= 1024);
    const float* in = isP ? g_pproj : g_lproj;
    const int mb = isP ? (m0 - 1024) : m0;
    const int colOff = isP ? 256 : 0;
    float* outp = isP ? g_B1 : g_A1;
    const int tid = threadIdx.x;
    const int tx = tid & 15, ty = tid >> 4;
    const int lr = tid >> 2, lc = (tid & 3) * 4;
    float acc[4][4] = {};
    for (int kt = 0; kt < 256; kt += 16) {
        float4 a4 = *(const float4*)&in[(mb + lr) * 256 + kt + lc];
        float4 b4 = *(const float4*)&W1[(n0 + lr) * 1024 + colOff + kt + lc];
        As[lc + 0][lr] = a4.x; As[lc + 1][lr] = a4.y; As[lc + 2][lr] = a4.z; As[lc + 3][lr] = a4.w;
        Bs[lc + 0][lr] = b4.x; Bs[lc + 1][lr] = b4.y; Bs[lc + 2][lr] = b4.z; Bs[lc + 3][lr] = b4.w;
        __syncthreads();
#pragma unroll
        for (int e = 0; e < 16; e++) {
            float4 av = *(const float4*)&As[e][ty * 4];
            float4 bv = *(const float4*)&Bs[e][tx * 4];
            acc[0][0] += av.x * bv.x; acc[0][1] += av.x * bv.y; acc[0][2] += av.x * bv.z; acc[0][3] += av.x * bv.w;
            acc[1][0] += av.y * bv.x; acc[1][1] += av.y * bv.y; acc[1][2] += av.y * bv.z; acc[1][3] += av.y * bv.w;
            acc[2][0] += av.z * bv.x; acc[2][1] += av.z * bv.y; acc[2][2] += av.z * bv.z; acc[2][3] += av.z * bv.w;
            acc[3][0] += av.w * bv.x; acc[3][1] += av.w * bv.y; acc[3][2] += av.w * bv.z; acc[3][3] += av.w * bv.w;
        }
        __syncthreads();
    }
#pragma unroll
    for (int ii = 0; ii < 4; ii++) {
#pragma unroll
        for (int jj = 0; jj < 4; jj++) {
            int n = n0 + tx * 4 + jj;
            float bv = isP ? 0.0f : b1[n];
            outp[(mb + ty * 4 + ii) * 128 + n] = acc[ii][jj] + bv;
        }
    }
}

// ---------------------------------------------------------------------------
// Main pair kernel with f32x2 packed FMA.
// Block = (b, 16 i, 16 j) = 256 pairs, 512 threads, micro-tile 8p x 8h.
// smem phase 1 (floats):
//   Ls[16][260] @0, Ps[16][260] @4160, Xs[32][256] @8320,
//   Wd (ull[32][132], duplicated {w,w}) @float 16512, A1s[16][132] @24960,
//   B1s[16][132] @27072  (ends 29184 floats = 116736 B)
// phase 2 (aliased):  Yt[128][264] @0 (135168 B), W2s[128][136] @33792 floats
// total dynamic smem 204800 B.
// ---------------------------------------------------------------------------
__global__ __launch_bounds__(512, 1) void pair_kernel(
    const float* __restrict__ W1, const float* __restrict__ W2,
    const float* __restrict__ W3, const float* __restrict__ b2g,
    const float* __restrict__ b3, float* __restrict__ out)
{
    extern __shared__ float sm[];
    float* Ls  = sm;
    float* Ps  = sm + 16 * 260;
    float* Xs  = sm + 2 * 16 * 260;
    unsigned long long* Wd = (unsigned long long*)(sm + 16512);  // [32][132] ull
    float* A1s = sm + 24960;
    float* B1s = sm + 27072;
    float* Yt  = sm;                       // phase 2
    float* W2s = sm + 128 * 264;           // phase 2 (disjoint from phase-1 region)

    const int tid = threadIdx.x;
    const int b  = blockIdx.z;
    const int it = blockIdx.y * 16;
    const int jt = blockIdx.x * 16;
    const int pg = tid >> 4;
    const int hg = tid & 15;
    const int p0 = pg * 8;
    const int h0 = hg * 8;
    const int my_i = p0 >> 4;
    const int j0 = p0 & 15;

    // ---- initial loads ----
    {
        const float* lsrc = g_lproj + (b * 256 + it) * 256;
        const float* psrc = g_pproj + (b * 256 + jt) * 256;
#pragma unroll
        for (int q = 0; q < 2; q++) {
            int f4 = q * 512 + tid;
            int r = f4 >> 6;
            int c = (f4 & 63) * 4;
            *(float4*)&Ls[r * 260 + c] = *(const float4*)&lsrc[r * 256 + c];
            *(float4*)&Ps[r * 260 + c] = *(const float4*)&psrc[r * 256 + c];
        }
        const float* a1src = g_A1 + (b * 256 + it) * 128;
        const float* b1src = g_B1 + (b * 256 + jt) * 128;
        {
            int f4 = tid;
            int r = f4 >> 5;
            int c = (f4 & 31) * 4;
            *(float4*)&A1s[r * 132 + c] = *(const float4*)&a1src[r * 128 + c];
            *(float4*)&B1s[r * 132 + c] = *(const float4*)&b1src[r * 128 + c];
        }
#pragma unroll
        for (int q = 0; q < 8; q++) {
            int f4 = q * 512 + tid;
            int f = f4 * 4;
            int g = f >> 7, h = f & 127;
            float4 v = *(const float4*)&W2[f];
            W2s[(h + 0) * 136 + g] = v.x;
            W2s[(h + 1) * 136 + g] = v.y;
            W2s[(h + 2) * 136 + g] = v.z;
            W2s[(h + 3) * 136 + g] = v.w;
        }
    }
    __syncthreads();

    unsigned long long acc2[8][4];
#pragma unroll
    for (int a = 0; a < 8; a++)
#pragma unroll
        for (int q = 0; q < 4; q++) acc2[a][q] = 0ull;

    const int xk = tid >> 4;
    const int xi = tid & 15;

    for (int kc = 0; kc < 512; kc += 32) {
        // build Xs[xk][xi*16+u]
        {
            int kk = kc + xk;
            if (kk < 256) {
                float lv = Ls[xi * 260 + kk];
#pragma unroll
                for (int u = 0; u < 16; u++)
                    Xs[xk * 256 + xi * 16 + u] = lv * Ps[u * 260 + kk];
            } else {
                int kd = kk - 256;
                float lv = Ls[xi * 260 + kd];
#pragma unroll
                for (int u = 0; u < 16; u++)
                    Xs[xk * 256 + xi * 16 + u] = fabsf(lv - Ps[u * 260 + kd]);
            }
        }
        // load Wd[k][h] = {w,w}, w = W1[h*1024 + 512 + kc + k]
        {
            int h = tid >> 2;
            int k0 = (tid & 3) * 8;
            const float* src = W1 + h * 1024 + 512 + kc + k0;
            float4 v0 = *(const float4*)(src);
            float4 v1 = *(const float4*)(src + 4);
            Wd[(k0 + 0) * 132 + h] = pack2(v0.x, v0.x);
            Wd[(k0 + 1) * 132 + h] = pack2(v0.y, v0.y);
            Wd[(k0 + 2) * 132 + h] = pack2(v0.z, v0.z);
            Wd[(k0 + 3) * 132 + h] = pack2(v0.w, v0.w);
            Wd[(k0 + 4) * 132 + h] = pack2(v1.x, v1.x);
            Wd[(k0 + 5) * 132 + h] = pack2(v1.y, v1.y);
            Wd[(k0 + 6) * 132 + h] = pack2(v1.z, v1.z);
            Wd[(k0 + 7) * 132 + h] = pack2(v1.w, v1.w);
        }
        __syncthreads();
#pragma unroll 4
        for (int k = 0; k < 32; k++) {
            ulonglong2 x0 = *(const ulonglong2*)&Xs[k * 256 + p0];
            ulonglong2 x1 = *(const ulonglong2*)&Xs[k * 256 + p0 + 4];
            const unsigned long long* wr = &Wd[k * 132 + h0];
            ulonglong2 w0 = *(const ulonglong2*)(wr);
            ulonglong2 w1 = *(const ulonglong2*)(wr + 2);
            ulonglong2 w2v = *(const ulonglong2*)(wr + 4);
            ulonglong2 w3v = *(const ulonglong2*)(wr + 6);
            unsigned long long xv[4] = {x0.x, x0.y, x1.x, x1.y};
            unsigned long long wv[8] = {w0.x, w0.y, w1.x, w1.y, w2v.x, w2v.y, w3v.x, w3v.y};
#pragma unroll
            for (int a = 0; a < 8; a++)
#pragma unroll
                for (int q = 0; q < 4; q++)
                    acc2[a][q] = fma2(wv[a], xv[q], acc2[a][q]);
        }
        __syncthreads();
    }

    // epilogue1: + A1 + B1, gelu -> regs, then store to Yt
    float yreg[8][8];
#pragma unroll
    for (int a = 0; a < 8; a++) {
        float av = A1s[my_i * 132 + h0 + a];
#pragma unroll
        for (int q = 0; q < 4; q++) {
            float lo, hi;
            unpack2(lo, hi, acc2[a][q]);
            int p = 2 * q;
            float z0 = lo + av + B1s[(j0 + p) * 132 + h0 + a];
            float z1 = hi + av + B1s[(j0 + p + 1) * 132 + h0 + a];
            yreg[a][p] = gelu_f(z0);
            yreg[a][p + 1] = gelu_f(z1);
        }
    }
    __syncthreads();
#pragma unroll
    for (int a = 0; a < 8; a++)
#pragma unroll
        for (int p = 0; p < 8; p++)
            Yt[(h0 + a) * 264 + p0 + p] = yreg[a][p];
    __syncthreads();

    // GEMM2: out2[g][p] = sum_h Yt[h][p] * W2s[h][g]   (f32x2, packed along p)
#pragma unroll
    for (int a = 0; a < 8; a++)
#pragma unroll
        for (int q = 0; q < 4; q++) acc2[a][q] = 0ull;
#pragma unroll 4
    for (int h = 0; h < 128; h++) {
        ulonglong2 y0 = *(const ulonglong2*)&Yt[h * 264 + p0];
        ulonglong2 y1 = *(const ulonglong2*)&Yt[h * 264 + p0 + 4];
        float4 wa = *(const float4*)&W2s[h * 136 + h0];
        float4 wb = *(const float4*)&W2s[h * 136 + h0 + 4];
        unsigned long long xv[4] = {y0.x, y0.y, y1.x, y1.y};
        unsigned long long wv[8] = {
            pack2(wa.x, wa.x), pack2(wa.y, wa.y), pack2(wa.z, wa.z), pack2(wa.w, wa.w),
            pack2(wb.x, wb.x), pack2(wb.y, wb.y), pack2(wb.z, wb.z), pack2(wb.w, wb.w)};
#pragma unroll
        for (int a = 0; a < 8; a++)
#pragma unroll
            for (int q = 0; q < 4; q++)
                acc2[a][q] = fma2(wv[a], xv[q], acc2[a][q]);
    }

    // epilogue2: + b2, gelu, dot with w3
    float part[8];
#pragma unroll
    for (int p = 0; p < 8; p++) part[p] = 0.0f;
#pragma unroll
    for (int gg = 0; gg < 8; gg++) {
        float w3v = W3[h0 + gg];
        float b2v = b2g[h0 + gg];
#pragma unroll
        for (int q = 0; q < 4; q++) {
            float lo, hi;
            unpack2(lo, hi, acc2[gg][q]);
            part[2 * q]     += w3v * gelu_f(lo + b2v);
            part[2 * q + 1] += w3v * gelu_f(hi + b2v);
        }
    }
#pragma unroll
    for (int off = 8; off >= 1; off >>= 1) {
#pragma unroll
        for (int p = 0; p < 8; p++)
            part[p] += __shfl_xor_sync(0xFFFFFFFFu, part[p], off);
    }
    if (hg == 0) {
        const int gi = it + my_i;
        const int lpad = g_lmask[b * 256 + gi];
        const float b3v = b3[0];
#pragma unroll
        for (int p = 0; p < 8; p++) {
            int j = jt + j0 + p;
            float v = part[p] + b3v;
            if (isnan(v)) v = 0.0f;
            else if (isinf(v)) v = (v > 0.0f) ? 20.0f : -20.0f;
            if (lpad || g_pmask[b * 256 + j]) v = -20.0f;
            int idx = 4 + (b * 65536 + gi * 256 + j);
            out[idx] = v;
            out[idx + 262144] = 1.0f / (1.0f + expf(-v));
        }
    }
}

// ---------------------------------------------------------------------------
// Top-k (k=100) per batch via radix-select + tie-aware exp-sum.
// ---------------------------------------------------------------------------
__device__ __forceinline__ int wredsum_i(int v) {
#pragma unroll
    for (int o = 16; o; o >>= 1) v += __shfl_xor_sync(0xFFFFFFFFu, v, o);
    return v;
}
__device__ __forceinline__ float wredsum_f(float v) {
#pragma unroll
    for (int o = 16; o; o >>= 1) v += __shfl_xor_sync(0xFFFFFFFFu, v, o);
    return v;
}
__device__ __forceinline__ float wredmax_f(float v) {
#pragma unroll
    for (int o = 16; o; o >>= 1) v = fmaxf(v, __shfl_xor_sync(0xFFFFFFFFu, v, o));
    return v;
}

__global__ __launch_bounds__(1024) void topk_kernel(float* out) {
    const int b = blockIdx.x;
    const float* data = out + 4 + b * NPAIR_B;
    const int tid = threadIdx.x, lane = tid & 31, wid = tid >> 5;
    __shared__ float sf[32];
    __shared__ float sf2[32];
    __shared__ int si[32];
    __shared__ float s_M;
    __shared__ int s_tot;

    float mx = -1e30f;
    for (int i = tid; i < NPAIR_B; i += 1024) mx = fmaxf(mx, data[i]);
    mx = wredmax_f(mx);
    if (lane == 0) sf[wid] = mx;
    __syncthreads();
    if (wid == 0) {
        float v = sf[lane];
        v = wredmax_f(v);
        if (lane == 0) s_M = v;
    }
    __syncthreads();
    const float M = s_M;

    unsigned prefix = 0u;
    for (int bit = 31; bit >= 0; --bit) {
        unsigned test = prefix | (1u << bit);
        int c = 0;
        for (int i = tid; i < NPAIR_B; i += 1024) {
            unsigned u = __float_as_uint(data[i]);
            unsigned k = (u & 0x80000000u) ? ~u : (u | 0x80000000u);
            c += (k >= test) ? 1 : 0;
        }
        c = wredsum_i(c);
        if (lane == 0) si[wid] = c;
        __syncthreads();
        if (wid == 0) {
            int v = si[lane];
            v = wredsum_i(v);
            if (lane == 0) s_tot = v;
        }
        __syncthreads();
        if (s_tot >= TOPK_K) prefix = test;
        __syncthreads();
    }

    float s1 = 0.0f, s2 = 0.0f;
    int cg = 0;
    for (int i = tid; i < NPAIR_B; i += 1024) {
        float v = data[i];
        unsigned u = __float_as_uint(v);
        unsigned k = (u & 0x80000000u) ? ~u : (u | 0x80000000u);
        if (k > prefix) {
            float e = expf(v - M);
            s1 += e; s2 += e * v; cg++;
        }
    }
    s1 = wredsum_f(s1);
    s2 = wredsum_f(s2);
    cg = wredsum_i(cg);
    if (lane == 0) { sf[wid] = s1; sf2[wid] = s2; si[wid] = cg; }
    __syncthreads();
    if (tid == 0) {
        float S1 = 0.0f, S2 = 0.0f;
        int CG = 0;
        for (int w = 0; w < 32; w++) { S1 += sf[w]; S2 += sf2[w]; CG += si[w]; }
        unsigned u = (prefix & 0x80000000u) ? (prefix & 0x7FFFFFFFu) : ~prefix;
        float vT = __uint_as_float(u);
        int r = TOPK_K - CG;
        float e = expf(vT - M);
        S1 += (float)r * e;
        S2 += (float)r * e * vT;
        out[b] = S2 / S1;
    }
}

// ---------------------------------------------------------------------------
extern "C" void kernel_launch(void* const* d_in, const int* in_sizes, int n_in,
                              void* d_out, int out_size)
{
    const float* ltok = (const float*)d_in[0];
    const float* ptok = (const float*)d_in[1];
    const void*  lpad = d_in[2];
    const void*  ppad = d_in[3];
    const float* Wl = (const float*)d_in[4];
    const float* bl = (const float*)d_in[5];
    const float* Wp = (const float*)d_in[6];
    const float* bp = (const float*)d_in[7];
    const float* W1 = (const float*)d_in[8];
    const float* b1 = (const float*)d_in[9];
    const float* W2 = (const float*)d_in[10];
    const float* b2 = (const float*)d_in[11];
    const float* W3 = (const float*)d_in[12];
    const float* b3 = (const float*)d_in[13];
    float* out = (float*)d_out;

    detect_kernel<<<2, 256>>>((const unsigned char*)lpad, (const unsigned char*)ppad);
    mask_kernel<<<2, 1024>>>(lpad, ppad);
    proj_kernel<<<dim3(4, 32), 256>>>(ltok, ptok, Wl, bl, Wp, bp);
    a1b1_kernel<<<dim3(2, 32), 256>>>(W1, b1);

    cudaFuncSetAttribute(pair_kernel, cudaFuncAttributeMaxDynamicSharedMemorySize, 204800);
    pair_kernel<<<dim3(16, 16, 4), 512, 204800>>>(W1, W2, W3, b2, b3, out);

    topk_kernel<<<4, 1024>>>(out);
}

// round 5
// speedup vs baseline: 5.2600x; 5.2559x over previous
#include <cuda_runtime.h>
#include <cuda_bf16.h>
#include <cstdint>
#include <math.h>

// ---------------------------------------------------------------------------
// PairwiseInteractionHead B=4, L=256, D=256, H=128, TOPK=100.
// Round 5: mma.sync (m16n8k16 bf16, fp32 accum) 3-pass hi/lo split GEMMs.
//   z1[h] = A1[i,h] + B1[j,h] + sum_k W1cd[h,k] X[(i,j),k]
//   X = [ l*p (k<256) ; |l-p| (k>=256) ], K=512; gelu;
//   z2 = Y @ W2^T (K=128); gelu; logit = z2.w3 + b3.
// Each operand x = xh + xl (bf16); D = Xh*Wh + Xh*Wl + Xl*Wh (err ~2^-18).
// ---------------------------------------------------------------------------

#define NB 4
#define NPAIR_B 65536
#define TOPK_K 100

__device__ float g_lproj[NB * 256 * 256];
__device__ float g_pproj[NB * 256 * 256];
__device__ float g_A1[NB * 256 * 128];
__device__ float g_B1[NB * 256 * 128];
__device__ int   g_lmask[NB * 256];
__device__ int   g_pmask[NB * 256];
__device__ int   g_flags[2];
__device__ __nv_bfloat16 g_W1hi[128 * 512];
__device__ __nv_bfloat16 g_W1lo[128 * 512];
__device__ __nv_bfloat16 g_W2hi[128 * 128];
__device__ __nv_bfloat16 g_W2lo[128 * 128];

__device__ __forceinline__ float gelu_f(float x) {
    return 0.5f * x * (1.0f + erff(x * 0.70710678118654752440f));
}

// -------------------- low-level helpers --------------------
__device__ __forceinline__ uint32_t smem_u32(const void* p) {
    uint32_t a;
    asm("{ .reg .u64 t; cvta.to.shared.u64 t, %1; cvt.u32.u64 %0, t; }" : "=r"(a) : "l"(p));
    return a;
}
__device__ __forceinline__ uint32_t packbf(float x0, float x1) {
    // packed: lo-half = x0, hi-half = x1
    uint32_t d;
    asm("cvt.rn.bf16x2.f32 %0, %1, %2;" : "=r"(d) : "f"(x1), "f"(x0));
    return d;
}
__device__ __forceinline__ float bf_lo_f(uint32_t v) { return __uint_as_float(v << 16); }
__device__ __forceinline__ float bf_hi_f(uint32_t v) { return __uint_as_float(v & 0xFFFF0000u); }
__device__ __forceinline__ void split8(const float* x, uint4& hi, uint4& lo) {
    uint32_t h0 = packbf(x[0], x[1]);
    uint32_t h1 = packbf(x[2], x[3]);
    uint32_t h2 = packbf(x[4], x[5]);
    uint32_t h3 = packbf(x[6], x[7]);
    hi = make_uint4(h0, h1, h2, h3);
    lo = make_uint4(
        packbf(x[0] - bf_lo_f(h0), x[1] - bf_hi_f(h0)),
        packbf(x[2] - bf_lo_f(h1), x[3] - bf_hi_f(h1)),
        packbf(x[4] - bf_lo_f(h2), x[5] - bf_hi_f(h2)),
        packbf(x[6] - bf_lo_f(h3), x[7] - bf_hi_f(h3)));
}
__device__ __forceinline__ void ldsm_x4(uint32_t* r, uint32_t addr) {
    asm volatile("ldmatrix.sync.aligned.m8n8.x4.shared.b16 {%0,%1,%2,%3}, [%4];"
        : "=r"(r[0]), "=r"(r[1]), "=r"(r[2]), "=r"(r[3]) : "r"(addr));
}
__device__ __forceinline__ void ldsm_x2(uint32_t* r, uint32_t addr) {
    asm volatile("ldmatrix.sync.aligned.m8n8.x2.shared.b16 {%0,%1}, [%2];"
        : "=r"(r[0]), "=r"(r[1]) : "r"(addr));
}
__device__ __forceinline__ void mma_bf16(float* c, const uint32_t* a, uint32_t b0, uint32_t b1) {
    asm volatile(
        "mma.sync.aligned.m16n8k16.row.col.f32.bf16.bf16.f32 "
        "{%0,%1,%2,%3}, {%4,%5,%6,%7}, {%8,%9}, {%0,%1,%2,%3};"
        : "+f"(c[0]), "+f"(c[1]), "+f"(c[2]), "+f"(c[3])
        : "r"(a[0]), "r"(a[1]), "r"(a[2]), "r"(a[3]), "r"(b0), "r"(b1));
}

// -------------------- pad-dtype detection + masks (proven) --------------------
__global__ void detect_kernel(const unsigned char* lp, const unsigned char* pp) {
    __shared__ int s_nonbin, s_oddnz, s_anynz;
    const unsigned char* p = blockIdx.x ? pp : lp;
    if (threadIdx.x == 0) { s_nonbin = 0; s_oddnz = 0; s_anynz = 0; }
    __syncthreads();
    int nonbin = 0, oddnz = 0, anynz = 0;
    for (int i = threadIdx.x; i < 1024; i += blockDim.x) {
        unsigned v = p[i];
        if (v) { anynz = 1; if (v > 1u) nonbin = 1; if (i & 3) oddnz = 1; }
    }
    if (nonbin) atomicOr(&s_nonbin, 1);
    if (oddnz)  atomicOr(&s_oddnz, 1);
    if (anynz)  atomicOr(&s_anynz, 1);
    __syncthreads();
    if (threadIdx.x == 0) {
        int f;
        if (!s_anynz) f = 0;
        else if (s_nonbin) f = 2;
        else if (s_oddnz) f = 1;
        else f = 3;
        g_flags[blockIdx.x] = f;
    }
}

__global__ void mask_kernel(const void* lp, const void* pp) {
    int buf = blockIdx.x;
    const void* p = buf ? pp : lp;
    int f = g_flags[buf];
    int i = threadIdx.x;
    int m;
    if (f == 0) m = 0;
    else if (f == 1) m = (((const unsigned char*)p)[i] != 0);
    else if (f == 2) m = (((const float*)p)[i] != 0.0f);
    else m = (((const int*)p)[i] != 0);
    (buf ? g_pmask : g_lmask)[i] = m;
}

// -------------------- weight split prep --------------------
__global__ void wprep_kernel(const float* __restrict__ W1, const float* __restrict__ W2) {
    int i = blockIdx.x * 256 + threadIdx.x;
    if (i < 128 * 512) {
        float w = W1[(i >> 9) * 1024 + 512 + (i & 511)];
        __nv_bfloat16 h = __float2bfloat16_rn(w);
        g_W1hi[i] = h;
        g_W1lo[i] = __float2bfloat16_rn(w - __bfloat162float(h));
    } else {
        int j = i - 128 * 512;
        if (j < 128 * 128) {
            float w = W2[j];
            __nv_bfloat16 h = __float2bfloat16_rn(w);
            g_W2hi[j] = h;
            g_W2lo[j] = __float2bfloat16_rn(w - __bfloat162float(h));
        }
    }
}

// -------------------- projection GEMM (R1, proven) --------------------
__global__ __launch_bounds__(256) void proj_kernel(
    const float* __restrict__ ltok, const float* __restrict__ ptok,
    const float* __restrict__ Wl, const float* __restrict__ bl,
    const float* __restrict__ Wp, const float* __restrict__ bp)
{
    __shared__ float As[16][68];
    __shared__ float Bs[16][68];
    const int n0 = blockIdx.x * 64;
    const int m0 = blockIdx.y * 64;
    const bool isP = (m0 >= 1024);
    const float* in   = isP ? ptok : ltok;
    const float* W    = isP ? Wp : Wl;
    const float* bias = isP ? bp : bl;
    const int mb = isP ? (m0 - 1024) : m0;
    float* outp = isP ? g_pproj : g_lproj;
    const int tid = threadIdx.x;
    const int tx = tid & 15, ty = tid >> 4;
    const int lr = tid >> 2, lc = (tid & 3) * 4;
    float acc[4][4] = {};
    for (int kt = 0; kt < 256; kt += 16) {
        float4 a4 = *(const float4*)&in[(mb + lr) * 256 + kt + lc];
        float4 b4 = *(const float4*)&W[(n0 + lr) * 256 + kt + lc];
        As[lc + 0][lr] = a4.x; As[lc + 1][lr] = a4.y; As[lc + 2][lr] = a4.z; As[lc + 3][lr] = a4.w;
        Bs[lc + 0][lr] = b4.x; Bs[lc + 1][lr] = b4.y; Bs[lc + 2][lr] = b4.z; Bs[lc + 3][lr] = b4.w;
        __syncthreads();
#pragma unroll
        for (int e = 0; e < 16; e++) {
            float4 av = *(const float4*)&As[e][ty * 4];
            float4 bv = *(const float4*)&Bs[e][tx * 4];
            acc[0][0] += av.x * bv.x; acc[0][1] += av.x * bv.y; acc[0][2] += av.x * bv.z; acc[0][3] += av.x * bv.w;
            acc[1][0] += av.y * bv.x; acc[1][1] += av.y * bv.y; acc[1][2] += av.y * bv.z; acc[1][3] += av.y * bv.w;
            acc[2][0] += av.z * bv.x; acc[2][1] += av.z * bv.y; acc[2][2] += av.z * bv.z; acc[2][3] += av.z * bv.w;
            acc[3][0] += av.w * bv.x; acc[3][1] += av.w * bv.y; acc[3][2] += av.w * bv.z; acc[3][3] += av.w * bv.w;
        }
        __syncthreads();
    }
#pragma unroll
    for (int ii = 0; ii < 4; ii++)
#pragma unroll
        for (int jj = 0; jj < 4; jj++) {
            int n = n0 + tx * 4 + jj;
            outp[(mb + ty * 4 + ii) * 256 + n] = acc[ii][jj] + bias[n];
        }
}

// -------------------- A1/B1 GEMM (R1, proven) --------------------
__global__ __launch_bounds__(256) void a1b1_kernel(
    const float* __restrict__ W1, const float* __restrict__ b1)
{
    __shared__ float As[16][68];
    __shared__ float Bs[16][68];
    const int n0 = blockIdx.x * 64;
    const int m0 = blockIdx.y * 64;
    const bool isP = (m0 >= 1024);
    const float* in = isP ? g_pproj : g_lproj;
    const int mb = isP ? (m0 - 1024) : m0;
    const int colOff = isP ? 256 : 0;
    float* outp = isP ? g_B1 : g_A1;
    const int tid = threadIdx.x;
    const int tx = tid & 15, ty = tid >> 4;
    const int lr = tid >> 2, lc = (tid & 3) * 4;
    float acc[4][4] = {};
    for (int kt = 0; kt < 256; kt += 16) {
        float4 a4 = *(const float4*)&in[(mb + lr) * 256 + kt + lc];
        float4 b4 = *(const float4*)&W1[(n0 + lr) * 1024 + colOff + kt + lc];
        As[lc + 0][lr] = a4.x; As[lc + 1][lr] = a4.y; As[lc + 2][lr] = a4.z; As[lc + 3][lr] = a4.w;
        Bs[lc + 0][lr] = b4.x; Bs[lc + 1][lr] = b4.y; Bs[lc + 2][lr] = b4.z; Bs[lc + 3][lr] = b4.w;
        __syncthreads();
#pragma unroll
        for (int e = 0; e < 16; e++) {
            float4 av = *(const float4*)&As[e][ty * 4];
            float4 bv = *(const float4*)&Bs[e][tx * 4];
            acc[0][0] += av.x * bv.x; acc[0][1] += av.x * bv.y; acc[0][2] += av.x * bv.z; acc[0][3] += av.x * bv.w;
            acc[1][0] += av.y * bv.x; acc[1][1] += av.y * bv.y; acc[1][2] += av.y * bv.z; acc[1][3] += av.y * bv.w;
            acc[2][0] += av.z * bv.x; acc[2][1] += av.z * bv.y; acc[2][2] += av.z * bv.z; acc[2][3] += av.z * bv.w;
            acc[3][0] += av.w * bv.x; acc[3][1] += av.w * bv.y; acc[3][2] += av.w * bv.z; acc[3][3] += av.w * bv.w;
        }
        __syncthreads();
    }
#pragma unroll
    for (int ii = 0; ii < 4; ii++)
#pragma unroll
        for (int jj = 0; jj < 4; jj++) {
            int n = n0 + tx * 4 + jj;
            float bv = isP ? 0.0f : b1[n];
            outp[(mb + ty * 4 + ii) * 128 + n] = acc[ii][jj] + bv;
        }
}

// -------------------- tensor-core pair kernel (mma.sync) --------------------
// 512 threads = 16 warps, warp grid 4(m)x4(n); warp tile 64 pairs x 32 h.
// CTA tile 256 pairs (16 i x 16 j) x 128 h. K chunks of 32, double-buffered.
// smem byte offsets:
#define SM_LS    0u        // [16][260] f32  = 16640
#define SM_PS    16640u    // [16][260] f32
#define SM_XH0   33280u    // [256][80B] bf16 rows (64B data + 16 pad)
#define SM_XL0   53760u
#define SM_XH1   74240u
#define SM_XL1   94720u
#define SM_WH0   115200u   // [128][80B]
#define SM_WL0   125440u
#define SM_WH1   135680u
#define SM_WL1   145920u
#define SM_A1    156160u   // [16][132] f32 = 8448
#define SM_B1    164608u   // [16][132] f32
// phase-2 aliases (after epilogue1a, A1/B1 dead):
#define SM_YH(c)  ((c) * 20480u)            // 4 chunks [256][80B]
#define SM_YL(c)  (81920u + (c) * 20480u)
#define SM_W2H    163840u  // [128][80B]
#define SM_W2L    174080u
#define SM_ZP     184320u  // [4][256] f32
#define SMEM_PAIR 188416

__global__ __launch_bounds__(512, 1) void pair_kernel(
    const float* __restrict__ b2g, const float* __restrict__ W3,
    const float* __restrict__ b3, float* __restrict__ out)
{
    extern __shared__ char smc[];
    float* Ls  = (float*)(smc + SM_LS);
    float* Ps  = (float*)(smc + SM_PS);
    float* A1s = (float*)(smc + SM_A1);
    float* B1s = (float*)(smc + SM_B1);
    const uint32_t sbase = smem_u32(smc);

    const int tid  = threadIdx.x;
    const int lane = tid & 31;
    const int wid  = tid >> 5;
    const int mw   = wid & 3;       // m warp (64 pairs)
    const int nw   = wid >> 2;      // n warp (32 h)
    const int b  = blockIdx.z;
    const int it = blockIdx.y * 16;
    const int jt = blockIdx.x * 16;

    const uint32_t xhOff[2] = {SM_XH0, SM_XH1};
    const uint32_t xlOff[2] = {SM_XL0, SM_XL1};
    const uint32_t whOff[2] = {SM_WH0, SM_WH1};
    const uint32_t wlOff[2] = {SM_WL0, SM_WL1};

    // ldmatrix lane address components
    const uint32_t a_row  = (lane & 7) + ((lane >> 3) & 1) * 8;
    const uint32_t a_colh = ((lane >> 4) & 1) * 16;
    const uint32_t b_row  = lane & 7;
    const uint32_t b_colh = ((lane >> 3) & 1) * 16;

    // ---- prologue loads ----
    {
        const float* lsrc = g_lproj + (size_t)(b * 256 + it) * 256;
        const float* psrc = g_pproj + (size_t)(b * 256 + jt) * 256;
#pragma unroll
        for (int q = 0; q < 2; q++) {
            int idx = q * 512 + tid;          // 1024 float4 per 16x256
            int r = idx >> 6;
            int c = (idx & 63) * 4;
            *(float4*)&Ls[r * 260 + c] = *(const float4*)&lsrc[r * 256 + c];
            *(float4*)&Ps[r * 260 + c] = *(const float4*)&psrc[r * 256 + c];
        }
        const float* a1src = g_A1 + (size_t)(b * 256 + it) * 128;
        const float* b1src = g_B1 + (size_t)(b * 256 + jt) * 128;
        int r = tid >> 5;
        int c = (tid & 31) * 4;
        *(float4*)&A1s[r * 132 + c] = *(const float4*)&a1src[r * 128 + c];
        *(float4*)&B1s[r * 132 + c] = *(const float4*)&b1src[r * 128 + c];
    }

    float acc[4][4][4];
#pragma unroll
    for (int mt = 0; mt < 4; mt++)
#pragma unroll
        for (int nt = 0; nt < 4; nt++)
#pragma unroll
            for (int r = 0; r < 4; r++) acc[mt][nt][r] = 0.0f;

    // X-build thread mapping: pair p = tid&255, k-half kh = tid>>8
    const int bp_ = tid & 255;
    const int bkh = tid >> 8;
    const float* blrow = Ls + (bp_ >> 4) * 260;
    const float* bprow = Ps + (bp_ & 15) * 260;

    // ---------- GEMM1: 16 K-chunks of 32 ----------
    __syncthreads();
    // build chunk 0 into buffer 0
    {
        const int kcol = bkh * 16;   // chunk 0, mul mode
        float x[16];
#pragma unroll
        for (int q = 0; q < 16; q += 4) {
            float4 lv = *(const float4*)(blrow + kcol + q);
            float4 pv = *(const float4*)(bprow + kcol + q);
            x[q + 0] = lv.x * pv.x; x[q + 1] = lv.y * pv.y;
            x[q + 2] = lv.z * pv.z; x[q + 3] = lv.w * pv.w;
        }
        uint4 h0, l0, h1, l1;
        split8(x, h0, l0);
        split8(x + 8, h1, l1);
        char* xhp = smc + SM_XH0 + bp_ * 80 + bkh * 32;
        char* xlp = smc + SM_XL0 + bp_ * 80 + bkh * 32;
        *(uint4*)(xhp) = h0; *(uint4*)(xhp + 16) = h1;
        *(uint4*)(xlp) = l0; *(uint4*)(xlp + 16) = l1;
        // W chunk 0
        const int wr = tid >> 2;
        const int ws = tid & 3;
        *(uint4*)(smc + SM_WH0 + wr * 80 + ws * 16) = *(const uint4*)(g_W1hi + wr * 512 + ws * 8);
        *(uint4*)(smc + SM_WL0 + wr * 80 + ws * 16) = *(const uint4*)(g_W1lo + wr * 512 + ws * 8);
    }
    __syncthreads();

    for (int c = 0; c < 16; c++) {
        const int s = c & 1;
        // build next chunk into other buffer
        if (c + 1 < 16) {
            const int cn = c + 1;
            const int sn = cn & 1;
            const bool mul = (cn < 8);
            const int kb = (mul ? cn * 32 : (cn - 8) * 32) + bkh * 16;
            float x[16];
#pragma unroll
            for (int q = 0; q < 16; q += 4) {
                float4 lv = *(const float4*)(blrow + kb + q);
                float4 pv = *(const float4*)(bprow + kb + q);
                if (mul) {
                    x[q + 0] = lv.x * pv.x; x[q + 1] = lv.y * pv.y;
                    x[q + 2] = lv.z * pv.z; x[q + 3] = lv.w * pv.w;
                } else {
                    x[q + 0] = fabsf(lv.x - pv.x); x[q + 1] = fabsf(lv.y - pv.y);
                    x[q + 2] = fabsf(lv.z - pv.z); x[q + 3] = fabsf(lv.w - pv.w);
                }
            }
            uint4 h0, l0, h1, l1;
            split8(x, h0, l0);
            split8(x + 8, h1, l1);
            char* xhp = smc + xhOff[sn] + bp_ * 80 + bkh * 32;
            char* xlp = smc + xlOff[sn] + bp_ * 80 + bkh * 32;
            *(uint4*)(xhp) = h0; *(uint4*)(xhp + 16) = h1;
            *(uint4*)(xlp) = l0; *(uint4*)(xlp + 16) = l1;
            const int wr = tid >> 2;
            const int ws = tid & 3;
            *(uint4*)(smc + whOff[sn] + wr * 80 + ws * 16) =
                *(const uint4*)(g_W1hi + wr * 512 + cn * 32 + ws * 8);
            *(uint4*)(smc + wlOff[sn] + wr * 80 + ws * 16) =
                *(const uint4*)(g_W1lo + wr * 512 + cn * 32 + ws * 8);
        }
        // mma on current chunk
#pragma unroll
        for (int ks = 0; ks < 2; ks++) {
            uint32_t ah[4][4], al[4][4];
#pragma unroll
            for (int mt = 0; mt < 4; mt++) {
                uint32_t rowa = (uint32_t)(mw * 64 + mt * 16) + a_row;
                ldsm_x4(ah[mt], sbase + xhOff[s] + rowa * 80 + ks * 32 + a_colh);
                ldsm_x4(al[mt], sbase + xlOff[s] + rowa * 80 + ks * 32 + a_colh);
            }
#pragma unroll
            for (int nt = 0; nt < 4; nt++) {
                uint32_t rowb = (uint32_t)(nw * 32 + nt * 8) + b_row;
                uint32_t bh[2], bl[2];
                ldsm_x2(bh, sbase + whOff[s] + rowb * 80 + ks * 32 + b_colh);
                ldsm_x2(bl, sbase + wlOff[s] + rowb * 80 + ks * 32 + b_colh);
#pragma unroll
                for (int mt = 0; mt < 4; mt++) {
                    mma_bf16(acc[mt][nt], ah[mt], bh[0], bh[1]);
                    mma_bf16(acc[mt][nt], ah[mt], bl[0], bl[1]);
                    mma_bf16(acc[mt][nt], al[mt], bh[0], bh[1]);
                }
            }
        }
        __syncthreads();
    }

    // ---------- epilogue 1a: z1 = acc + A1 + B1, gelu (regs) ----------
#pragma unroll
    for (int mt = 0; mt < 4; mt++) {
#pragma unroll
        for (int rh = 0; rh < 2; rh++) {
            int row = mw * 64 + mt * 16 + (lane >> 2) + rh * 8;
            int il = row >> 4, jl = row & 15;
#pragma unroll
            for (int nt = 0; nt < 4; nt++) {
                int colb = nw * 32 + nt * 8 + (lane & 3) * 2;
                float2 a1v = *(const float2*)&A1s[il * 132 + colb];
                float2 b1v = *(const float2*)&B1s[jl * 132 + colb];
                acc[mt][nt][rh * 2 + 0] = gelu_f(acc[mt][nt][rh * 2 + 0] + a1v.x + b1v.x);
                acc[mt][nt][rh * 2 + 1] = gelu_f(acc[mt][nt][rh * 2 + 1] + a1v.y + b1v.y);
            }
        }
    }
    __syncthreads();   // A1/B1 consumed; Y region (aliases phase-1 smem) safe

    // ---------- epilogue 1b: split Y to smem chunk nw ----------
#pragma unroll
    for (int mt = 0; mt < 4; mt++) {
#pragma unroll
        for (int nt = 0; nt < 4; nt++) {
#pragma unroll
            for (int rh = 0; rh < 2; rh++) {
                int row = mw * 64 + mt * 16 + (lane >> 2) + rh * 8;
                int cloc = nt * 8 + (lane & 3) * 2;      // col within chunk nw
                float y0 = acc[mt][nt][rh * 2 + 0];
                float y1 = acc[mt][nt][rh * 2 + 1];
                uint32_t hp = packbf(y0, y1);
                uint32_t lp2 = packbf(y0 - bf_lo_f(hp), y1 - bf_hi_f(hp));
                *(uint32_t*)(smc + SM_YH(nw) + row * 80 + cloc * 2) = hp;
                *(uint32_t*)(smc + SM_YL(nw) + row * 80 + cloc * 2) = lp2;
            }
        }
    }

    // reset accumulators for GEMM2
#pragma unroll
    for (int mt = 0; mt < 4; mt++)
#pragma unroll
        for (int nt = 0; nt < 4; nt++)
#pragma unroll
            for (int r = 0; r < 4; r++) acc[mt][nt][r] = 0.0f;
    __syncthreads();

    // ---------- GEMM2: K=128 in 4 chunks of 32 (Y chunks ready) ----------
    for (int kc = 0; kc < 4; kc++) {
        {   // load W2 chunk
            const int wr = tid >> 2;
            const int ws = tid & 3;
            *(uint4*)(smc + SM_W2H + wr * 80 + ws * 16) =
                *(const uint4*)(g_W2hi + wr * 128 + kc * 32 + ws * 8);
            *(uint4*)(smc + SM_W2L + wr * 80 + ws * 16) =
                *(const uint4*)(g_W2lo + wr * 128 + kc * 32 + ws * 8);
        }
        __syncthreads();
#pragma unroll
        for (int ks = 0; ks < 2; ks++) {
            uint32_t ah[4][4], al[4][4];
#pragma unroll
            for (int mt = 0; mt < 4; mt++) {
                uint32_t rowa = (uint32_t)(mw * 64 + mt * 16) + a_row;
                ldsm_x4(ah[mt], sbase + SM_YH(kc) + rowa * 80 + ks * 32 + a_colh);
                ldsm_x4(al[mt], sbase + SM_YL(kc) + rowa * 80 + ks * 32 + a_colh);
            }
#pragma unroll
            for (int nt = 0; nt < 4; nt++) {
                uint32_t rowb = (uint32_t)(nw * 32 + nt * 8) + b_row;
                uint32_t bh[2], bl[2];
                ldsm_x2(bh, sbase + SM_W2H + rowb * 80 + ks * 32 + b_colh);
                ldsm_x2(bl, sbase + SM_W2L + rowb * 80 + ks * 32 + b_colh);
#pragma unroll
                for (int mt = 0; mt < 4; mt++) {
                    mma_bf16(acc[mt][nt], ah[mt], bh[0], bh[1]);
                    mma_bf16(acc[mt][nt], ah[mt], bl[0], bl[1]);
                    mma_bf16(acc[mt][nt], al[mt], bh[0], bh[1]);
                }
            }
        }
        __syncthreads();
    }

    // ---------- epilogue 2: gelu + w3 dot, reduce, outputs ----------
    {
        float part[4][2];
#pragma unroll
        for (int mt = 0; mt < 4; mt++) { part[mt][0] = 0.0f; part[mt][1] = 0.0f; }
#pragma unroll
        for (int nt = 0; nt < 4; nt++) {
            int colb = nw * 32 + nt * 8 + (lane & 3) * 2;
            float w3a = __ldg(W3 + colb), w3b = __ldg(W3 + colb + 1);
            float b2a = __ldg(b2g + colb), b2b = __ldg(b2g + colb + 1);
#pragma unroll
            for (int mt = 0; mt < 4; mt++) {
                part[mt][0] += w3a * gelu_f(acc[mt][nt][0] + b2a) + w3b * gelu_f(acc[mt][nt][1] + b2b);
                part[mt][1] += w3a * gelu_f(acc[mt][nt][2] + b2a) + w3b * gelu_f(acc[mt][nt][3] + b2b);
            }
        }
        // reduce across the 4 lanes sharing a row (lane&3)
#pragma unroll
        for (int off = 1; off <= 2; off <<= 1) {
#pragma unroll
            for (int mt = 0; mt < 4; mt++) {
                part[mt][0] += __shfl_xor_sync(0xFFFFFFFFu, part[mt][0], off);
                part[mt][1] += __shfl_xor_sync(0xFFFFFFFFu, part[mt][1], off);
            }
        }
        if ((lane & 3) == 0) {
            float* ZP = (float*)(smc + SM_ZP);
#pragma unroll
            for (int mt = 0; mt < 4; mt++) {
                int row0 = mw * 64 + mt * 16 + (lane >> 2);
                ZP[nw * 256 + row0]     = part[mt][0];
                ZP[nw * 256 + row0 + 8] = part[mt][1];
            }
        }
    }
    __syncthreads();
    if (tid < 256) {
        const float* ZP = (const float*)(smc + SM_ZP);
        float v = ZP[tid] + ZP[256 + tid] + ZP[512 + tid] + ZP[768 + tid] + b3[0];
        if (isnan(v)) v = 0.0f;
        else if (isinf(v)) v = (v > 0.0f) ? 20.0f : -20.0f;
        const int gi = it + (tid >> 4);
        const int gj = jt + (tid & 15);
        if (g_lmask[b * 256 + gi] || g_pmask[b * 256 + gj]) v = -20.0f;
        const int idx = 4 + (b * 65536 + gi * 256 + gj);
        out[idx] = v;
        out[idx + 262144] = 1.0f / (1.0f + expf(-v));
    }
}

// -------------------- top-k: 4-pass byte radix + tie-aware exp-sum --------------------
__device__ __forceinline__ int wredsum_i(int v) {
#pragma unroll
    for (int o = 16; o; o >>= 1) v += __shfl_xor_sync(0xFFFFFFFFu, v, o);
    return v;
}
__device__ __forceinline__ float wredsum_f(float v) {
#pragma unroll
    for (int o = 16; o; o >>= 1) v += __shfl_xor_sync(0xFFFFFFFFu, v, o);
    return v;
}

__global__ __launch_bounds__(1024) void topk_kernel(float* out) {
    const int b = blockIdx.x;
    const float* data = out + 4 + b * NPAIR_B;
    const int tid = threadIdx.x, lane = tid & 31, wid = tid >> 5;
    __shared__ int hist[256];
    __shared__ unsigned s_pref;
    __shared__ int s_above;
    __shared__ float sf[32], sf2[32];
    __shared__ int si[32];

    unsigned prefix = 0u;
    int above = 0;
    for (int pass = 0; pass < 4; pass++) {
        const int bpos = 24 - 8 * pass;
        if (tid < 256) hist[tid] = 0;
        __syncthreads();
        const unsigned maskHi = (pass == 0) ? 0u : (0xFFFFFFFFu << (bpos + 8));
        for (int i = tid; i < NPAIR_B; i += 1024) {
            unsigned u = __float_as_uint(data[i]);
            unsigned k = (u & 0x80000000u) ? ~u : (u | 0x80000000u);
            if (((k ^ prefix) & maskHi) == 0)
                atomicAdd(&hist[(k >> bpos) & 255], 1);
        }
        __syncthreads();
        if (tid == 0) {
            int run = 0, chosen = 0, abv = above;
            for (int x = 255; x >= 0; --x) {
                int nr = run + hist[x];
                if (above + nr >= TOPK_K) { chosen = x; abv = above + run; break; }
                run = nr;
            }
            s_pref = prefix | ((unsigned)chosen << bpos);
            s_above = abv;
        }
        __syncthreads();
        prefix = s_pref;
        above = s_above;
        __syncthreads();
    }

    // threshold value (the 100th-largest key == prefix exactly)
    unsigned ut = (prefix & 0x80000000u) ? (prefix & 0x7FFFFFFFu) : ~prefix;
    const float vT = __uint_as_float(ut);

    float s1 = 0.0f, s2 = 0.0f;
    int cg = 0;
    for (int i = tid; i < NPAIR_B; i += 1024) {
        float v = data[i];
        unsigned u = __float_as_uint(v);
        unsigned k = (u & 0x80000000u) ? ~u : (u | 0x80000000u);
        if (k > prefix) {
            float e = expf(v - vT);
            s1 += e; s2 += e * v; cg++;
        }
    }
    s1 = wredsum_f(s1);
    s2 = wredsum_f(s2);
    cg = wredsum_i(cg);
    if (lane == 0) { sf[wid] = s1; sf2[wid] = s2; si[wid] = cg; }
    __syncthreads();
    if (tid == 0) {
        float S1 = 0.0f, S2 = 0.0f;
        int CG = 0;
        for (int w = 0; w < 32; w++) { S1 += sf[w]; S2 += sf2[w]; CG += si[w]; }
        int r = TOPK_K - CG;          // ties at threshold
        S1 += (float)r * 1.0f;        // exp(vT - vT) = 1
        S2 += (float)r * vT;
        out[b] = S2 / S1;
    }
}

// ---------------------------------------------------------------------------
extern "C" void kernel_launch(void* const* d_in, const int* in_sizes, int n_in,
                              void* d_out, int out_size)
{
    const float* ltok = (const float*)d_in[0];
    const float* ptok = (const float*)d_in[1];
    const void*  lpad = d_in[2];
    const void*  ppad = d_in[3];
    const float* Wl = (const float*)d_in[4];
    const float* bl = (const float*)d_in[5];
    const float* Wp = (const float*)d_in[6];
    const float* bp = (const float*)d_in[7];
    const float* W1 = (const float*)d_in[8];
    const float* b1 = (const float*)d_in[9];
    const float* W2 = (const float*)d_in[10];
    const float* b2 = (const float*)d_in[11];
    const float* W3 = (const float*)d_in[12];
    const float* b3 = (const float*)d_in[13];
    float* out = (float*)d_out;

    detect_kernel<<<2, 256>>>((const unsigned char*)lpad, (const unsigned char*)ppad);
    mask_kernel<<<2, 1024>>>(lpad, ppad);
    wprep_kernel<<<320, 256>>>(W1, W2);
    proj_kernel<<<dim3(4, 32), 256>>>(ltok, ptok, Wl, bl, Wp, bp);
    a1b1_kernel<<<dim3(2, 32), 256>>>(W1, b1);

    cudaFuncSetAttribute(pair_kernel, cudaFuncAttributeMaxDynamicSharedMemorySize, SMEM_PAIR);
    pair_kernel<<<dim3(16, 16, 4), 512, SMEM_PAIR>>>(b2, W3, b3, out);

    topk_kernel<<<4, 1024>>>(out);
}

// round 6
// speedup vs baseline: 6.6886x; 1.2716x over previous
#include <cuda_runtime.h>
#include <cuda_fp16.h>
#include <cstdint>
#include <math.h>

// ---------------------------------------------------------------------------
// PairwiseInteractionHead B=4, L=256, D=256, H=128, TOPK=100.
// Round 6: mma.sync m16n8k16 fp16 2-pass: X exact (hi+lo fp16), W fp16-hi only.
//   D = Xh@Wh + Xl@Wh = X @ W_fp16 ; error = W quantization (~2^-11, attenuated)
// X and Y scaled by 32 so fp16 lo fragments stay normal; epilogues scale 1/32.
// ---------------------------------------------------------------------------

#define NB 4
#define NPAIR_B 65536
#define TOPK_K 100
#define XSCALE 32.0f
#define XINV   0.03125f

__device__ float g_lproj[NB * 256 * 256];
__device__ float g_pproj[NB * 256 * 256];
__device__ float g_A1[NB * 256 * 128];
__device__ float g_B1[NB * 256 * 128];
__device__ int   g_lmask[NB * 256];
__device__ int   g_pmask[NB * 256];
__device__ int   g_flags[2];
__device__ __half g_W1h[128 * 512];
__device__ __half g_W2h[128 * 128];

__device__ __forceinline__ float gelu_f(float x) {
    return 0.5f * x * (1.0f + erff(x * 0.70710678118654752440f));
}

// -------------------- low-level helpers --------------------
__device__ __forceinline__ uint32_t smem_u32(const void* p) {
    uint32_t a;
    asm("{ .reg .u64 t; cvta.to.shared.u64 t, %1; cvt.u32.u64 %0, t; }" : "=r"(a) : "l"(p));
    return a;
}
__device__ __forceinline__ uint32_t packh(float x0, float x1) {
    // packed fp16x2: lo-half = x0, hi-half = x1 (same operand pattern as R5 bf16, proven)
    uint32_t d;
    asm("cvt.rn.f16x2.f32 %0, %1, %2;" : "=r"(d) : "f"(x1), "f"(x0));
    return d;
}
__device__ __forceinline__ float h_lo(uint32_t v) {
    return __half2float(__ushort_as_half((unsigned short)(v & 0xFFFFu)));
}
__device__ __forceinline__ float h_hi(uint32_t v) {
    return __half2float(__ushort_as_half((unsigned short)(v >> 16)));
}
__device__ __forceinline__ void split8h(const float* x, uint4& hi, uint4& lo) {
    uint32_t h0 = packh(x[0], x[1]);
    uint32_t h1 = packh(x[2], x[3]);
    uint32_t h2 = packh(x[4], x[5]);
    uint32_t h3 = packh(x[6], x[7]);
    hi = make_uint4(h0, h1, h2, h3);
    lo = make_uint4(
        packh(x[0] - h_lo(h0), x[1] - h_hi(h0)),
        packh(x[2] - h_lo(h1), x[3] - h_hi(h1)),
        packh(x[4] - h_lo(h2), x[5] - h_hi(h2)),
        packh(x[6] - h_lo(h3), x[7] - h_hi(h3)));
}
__device__ __forceinline__ void ldsm_x4(uint32_t* r, uint32_t addr) {
    asm volatile("ldmatrix.sync.aligned.m8n8.x4.shared.b16 {%0,%1,%2,%3}, [%4];"
        : "=r"(r[0]), "=r"(r[1]), "=r"(r[2]), "=r"(r[3]) : "r"(addr));
}
__device__ __forceinline__ void ldsm_x2(uint32_t* r, uint32_t addr) {
    asm volatile("ldmatrix.sync.aligned.m8n8.x2.shared.b16 {%0,%1}, [%2];"
        : "=r"(r[0]), "=r"(r[1]) : "r"(addr));
}
__device__ __forceinline__ void mma_f16(float* c, const uint32_t* a, uint32_t b0, uint32_t b1) {
    asm volatile(
        "mma.sync.aligned.m16n8k16.row.col.f32.f16.f16.f32 "
        "{%0,%1,%2,%3}, {%4,%5,%6,%7}, {%8,%9}, {%0,%1,%2,%3};"
        : "+f"(c[0]), "+f"(c[1]), "+f"(c[2]), "+f"(c[3])
        : "r"(a[0]), "r"(a[1]), "r"(a[2]), "r"(a[3]), "r"(b0), "r"(b1));
}

// -------------------- pad-dtype detection + masks (proven) --------------------
__global__ void detect_kernel(const unsigned char* lp, const unsigned char* pp) {
    __shared__ int s_nonbin, s_oddnz, s_anynz;
    const unsigned char* p = blockIdx.x ? pp : lp;
    if (threadIdx.x == 0) { s_nonbin = 0; s_oddnz = 0; s_anynz = 0; }
    __syncthreads();
    int nonbin = 0, oddnz = 0, anynz = 0;
    for (int i = threadIdx.x; i < 1024; i += blockDim.x) {
        unsigned v = p[i];
        if (v) { anynz = 1; if (v > 1u) nonbin = 1; if (i & 3) oddnz = 1; }
    }
    if (nonbin) atomicOr(&s_nonbin, 1);
    if (oddnz)  atomicOr(&s_oddnz, 1);
    if (anynz)  atomicOr(&s_anynz, 1);
    __syncthreads();
    if (threadIdx.x == 0) {
        int f;
        if (!s_anynz) f = 0;
        else if (s_nonbin) f = 2;
        else if (s_oddnz) f = 1;
        else f = 3;
        g_flags[blockIdx.x] = f;
    }
}

__global__ void mask_kernel(const void* lp, const void* pp) {
    int buf = blockIdx.x;
    const void* p = buf ? pp : lp;
    int f = g_flags[buf];
    int i = threadIdx.x;
    int m;
    if (f == 0) m = 0;
    else if (f == 1) m = (((const unsigned char*)p)[i] != 0);
    else if (f == 2) m = (((const float*)p)[i] != 0.0f);
    else m = (((const int*)p)[i] != 0);
    (buf ? g_pmask : g_lmask)[i] = m;
}

// -------------------- weight fp16 prep --------------------
__global__ void wprep_kernel(const float* __restrict__ W1, const float* __restrict__ W2) {
    int i = blockIdx.x * 256 + threadIdx.x;
    if (i < 128 * 512) {
        g_W1h[i] = __float2half_rn(W1[(i >> 9) * 1024 + 512 + (i & 511)]);
    } else {
        int j = i - 128 * 512;
        if (j < 128 * 128) g_W2h[j] = __float2half_rn(W2[j]);
    }
}

// -------------------- projection GEMM (R1, proven) --------------------
__global__ __launch_bounds__(256) void proj_kernel(
    const float* __restrict__ ltok, const float* __restrict__ ptok,
    const float* __restrict__ Wl, const float* __restrict__ bl,
    const float* __restrict__ Wp, const float* __restrict__ bp)
{
    __shared__ float As[16][68];
    __shared__ float Bs[16][68];
    const int n0 = blockIdx.x * 64;
    const int m0 = blockIdx.y * 64;
    const bool isP = (m0 >= 1024);
    const float* in   = isP ? ptok : ltok;
    const float* W    = isP ? Wp : Wl;
    const float* bias = isP ? bp : bl;
    const int mb = isP ? (m0 - 1024) : m0;
    float* outp = isP ? g_pproj : g_lproj;
    const int tid = threadIdx.x;
    const int tx = tid & 15, ty = tid >> 4;
    const int lr = tid >> 2, lc = (tid & 3) * 4;
    float acc[4][4] = {};
    for (int kt = 0; kt < 256; kt += 16) {
        float4 a4 = *(const float4*)&in[(mb + lr) * 256 + kt + lc];
        float4 b4 = *(const float4*)&W[(n0 + lr) * 256 + kt + lc];
        As[lc + 0][lr] = a4.x; As[lc + 1][lr] = a4.y; As[lc + 2][lr] = a4.z; As[lc + 3][lr] = a4.w;
        Bs[lc + 0][lr] = b4.x; Bs[lc + 1][lr] = b4.y; Bs[lc + 2][lr] = b4.z; Bs[lc + 3][lr] = b4.w;
        __syncthreads();
#pragma unroll
        for (int e = 0; e < 16; e++) {
            float4 av = *(const float4*)&As[e][ty * 4];
            float4 bv = *(const float4*)&Bs[e][tx * 4];
            acc[0][0] += av.x * bv.x; acc[0][1] += av.x * bv.y; acc[0][2] += av.x * bv.z; acc[0][3] += av.x * bv.w;
            acc[1][0] += av.y * bv.x; acc[1][1] += av.y * bv.y; acc[1][2] += av.y * bv.z; acc[1][3] += av.y * bv.w;
            acc[2][0] += av.z * bv.x; acc[2][1] += av.z * bv.y; acc[2][2] += av.z * bv.z; acc[2][3] += av.z * bv.w;
            acc[3][0] += av.w * bv.x; acc[3][1] += av.w * bv.y; acc[3][2] += av.w * bv.z; acc[3][3] += av.w * bv.w;
        }
        __syncthreads();
    }
#pragma unroll
    for (int ii = 0; ii < 4; ii++)
#pragma unroll
        for (int jj = 0; jj < 4; jj++) {
            int n = n0 + tx * 4 + jj;
            outp[(mb + ty * 4 + ii) * 256 + n] = acc[ii][jj] + bias[n];
        }
}

// -------------------- A1/B1 GEMM (R1, proven) --------------------
__global__ __launch_bounds__(256) void a1b1_kernel(
    const float* __restrict__ W1, const float* __restrict__ b1)
{
    __shared__ float As[16][68];
    __shared__ float Bs[16][68];
    const int n0 = blockIdx.x * 64;
    const int m0 = blockIdx.y * 64;
    const bool isP = (m0 >= 1024);
    const float* in = isP ? g_pproj : g_lproj;
    const int mb = isP ? (m0 - 1024) : m0;
    const int colOff = isP ? 256 : 0;
    float* outp = isP ? g_B1 : g_A1;
    const int tid = threadIdx.x;
    const int tx = tid & 15, ty = tid >> 4;
    const int lr = tid >> 2, lc = (tid & 3) * 4;
    float acc[4][4] = {};
    for (int kt = 0; kt < 256; kt += 16) {
        float4 a4 = *(const float4*)&in[(mb + lr) * 256 + kt + lc];
        float4 b4 = *(const float4*)&W1[(n0 + lr) * 1024 + colOff + kt + lc];
        As[lc + 0][lr] = a4.x; As[lc + 1][lr] = a4.y; As[lc + 2][lr] = a4.z; As[lc + 3][lr] = a4.w;
        Bs[lc + 0][lr] = b4.x; Bs[lc + 1][lr] = b4.y; Bs[lc + 2][lr] = b4.z; Bs[lc + 3][lr] = b4.w;
        __syncthreads();
#pragma unroll
        for (int e = 0; e < 16; e++) {
            float4 av = *(const float4*)&As[e][ty * 4];
            float4 bv = *(const float4*)&Bs[e][tx * 4];
            acc[0][0] += av.x * bv.x; acc[0][1] += av.x * bv.y; acc[0][2] += av.x * bv.z; acc[0][3] += av.x * bv.w;
            acc[1][0] += av.y * bv.x; acc[1][1] += av.y * bv.y; acc[1][2] += av.y * bv.z; acc[1][3] += av.y * bv.w;
            acc[2][0] += av.z * bv.x; acc[2][1] += av.z * bv.y; acc[2][2] += av.z * bv.z; acc[2][3] += av.z * bv.w;
            acc[3][0] += av.w * bv.x; acc[3][1] += av.w * bv.y; acc[3][2] += av.w * bv.z; acc[3][3] += av.w * bv.w;
        }
        __syncthreads();
    }
#pragma unroll
    for (int ii = 0; ii < 4; ii++)
#pragma unroll
        for (int jj = 0; jj < 4; jj++) {
            int n = n0 + tx * 4 + jj;
            float bv = isP ? 0.0f : b1[n];
            outp[(mb + ty * 4 + ii) * 128 + n] = acc[ii][jj] + bv;
        }
}

// -------------------- tensor-core pair kernel (mma.sync fp16, 2-pass) ------
// 512 threads = 16 warps, 4(m)x4(n); warp tile 64 pairs x 32 h.
// smem byte offsets (phase 1):
#define SM_LS    0u        // [16][260] f32
#define SM_PS    16640u
#define SM_XH0   33280u    // [256][80B]
#define SM_XL0   53760u
#define SM_XH1   74240u
#define SM_XL1   94720u
#define SM_WH0   115200u   // [128][80B]
#define SM_WH1   125440u
#define SM_A1    135680u   // [16][132] f32
#define SM_B1    144128u
// phase-2 aliases (A1/B1 consumed before Y writes):
#define SM_YH(c)  ((c) * 20480u)
#define SM_YL(c)  (81920u + (c) * 20480u)
#define SM_W2H    163840u
#define SM_ZP     174080u  // [4][256] f32
#define SMEM_PAIR 178176

__global__ __launch_bounds__(512, 1) void pair_kernel(
    const float* __restrict__ b2g, const float* __restrict__ W3,
    const float* __restrict__ b3, float* __restrict__ out)
{
    extern __shared__ char smc[];
    float* Ls  = (float*)(smc + SM_LS);
    float* Ps  = (float*)(smc + SM_PS);
    float* A1s = (float*)(smc + SM_A1);
    float* B1s = (float*)(smc + SM_B1);
    const uint32_t sbase = smem_u32(smc);

    const int tid  = threadIdx.x;
    const int lane = tid & 31;
    const int wid  = tid >> 5;
    const int mw   = wid & 3;
    const int nw   = wid >> 2;
    const int b  = blockIdx.z;
    const int it = blockIdx.y * 16;
    const int jt = blockIdx.x * 16;

    const uint32_t xhOff[2] = {SM_XH0, SM_XH1};
    const uint32_t xlOff[2] = {SM_XL0, SM_XL1};
    const uint32_t whOff[2] = {SM_WH0, SM_WH1};

    const uint32_t a_row  = (lane & 7) + ((lane >> 3) & 1) * 8;
    const uint32_t a_colh = ((lane >> 4) & 1) * 16;
    const uint32_t b_row  = lane & 7;
    const uint32_t b_colh = ((lane >> 3) & 1) * 16;

    // ---- prologue loads ----
    {
        const float* lsrc = g_lproj + (size_t)(b * 256 + it) * 256;
        const float* psrc = g_pproj + (size_t)(b * 256 + jt) * 256;
#pragma unroll
        for (int q = 0; q < 2; q++) {
            int idx = q * 512 + tid;
            int r = idx >> 6;
            int c = (idx & 63) * 4;
            *(float4*)&Ls[r * 260 + c] = *(const float4*)&lsrc[r * 256 + c];
            *(float4*)&Ps[r * 260 + c] = *(const float4*)&psrc[r * 256 + c];
        }
        const float* a1src = g_A1 + (size_t)(b * 256 + it) * 128;
        const float* b1src = g_B1 + (size_t)(b * 256 + jt) * 128;
        int r = tid >> 5;
        int c = (tid & 31) * 4;
        *(float4*)&A1s[r * 132 + c] = *(const float4*)&a1src[r * 128 + c];
        *(float4*)&B1s[r * 132 + c] = *(const float4*)&b1src[r * 128 + c];
    }

    float acc[4][4][4];
#pragma unroll
    for (int mt = 0; mt < 4; mt++)
#pragma unroll
        for (int nt = 0; nt < 4; nt++)
#pragma unroll
            for (int r = 0; r < 4; r++) acc[mt][nt][r] = 0.0f;

    const int bp_ = tid & 255;
    const int bkh = tid >> 8;
    const float* blrow = Ls + (bp_ >> 4) * 260;
    const float* bprow = Ps + (bp_ & 15) * 260;

    // ---------- GEMM1: 16 K-chunks of 32 ----------
    __syncthreads();
    {
        const int kcol = bkh * 16;
        float x[16];
#pragma unroll
        for (int q = 0; q < 16; q += 4) {
            float4 lv = *(const float4*)(blrow + kcol + q);
            float4 pv = *(const float4*)(bprow + kcol + q);
            x[q + 0] = XSCALE * (lv.x * pv.x); x[q + 1] = XSCALE * (lv.y * pv.y);
            x[q + 2] = XSCALE * (lv.z * pv.z); x[q + 3] = XSCALE * (lv.w * pv.w);
        }
        uint4 h0, l0, h1, l1;
        split8h(x, h0, l0);
        split8h(x + 8, h1, l1);
        char* xhp = smc + SM_XH0 + bp_ * 80 + bkh * 32;
        char* xlp = smc + SM_XL0 + bp_ * 80 + bkh * 32;
        *(uint4*)(xhp) = h0; *(uint4*)(xhp + 16) = h1;
        *(uint4*)(xlp) = l0; *(uint4*)(xlp + 16) = l1;
        const int wr = tid >> 2;
        const int ws = tid & 3;
        *(uint4*)(smc + SM_WH0 + wr * 80 + ws * 16) = *(const uint4*)(g_W1h + wr * 512 + ws * 8);
    }
    __syncthreads();

    for (int c = 0; c < 16; c++) {
        const int s = c & 1;
        if (c + 1 < 16) {
            const int cn = c + 1;
            const int sn = cn & 1;
            const bool mul = (cn < 8);
            const int kb = (mul ? cn * 32 : (cn - 8) * 32) + bkh * 16;
            float x[16];
#pragma unroll
            for (int q = 0; q < 16; q += 4) {
                float4 lv = *(const float4*)(blrow + kb + q);
                float4 pv = *(const float4*)(bprow + kb + q);
                if (mul) {
                    x[q + 0] = XSCALE * (lv.x * pv.x); x[q + 1] = XSCALE * (lv.y * pv.y);
                    x[q + 2] = XSCALE * (lv.z * pv.z); x[q + 3] = XSCALE * (lv.w * pv.w);
                } else {
                    x[q + 0] = XSCALE * fabsf(lv.x - pv.x); x[q + 1] = XSCALE * fabsf(lv.y - pv.y);
                    x[q + 2] = XSCALE * fabsf(lv.z - pv.z); x[q + 3] = XSCALE * fabsf(lv.w - pv.w);
                }
            }
            uint4 h0, l0, h1, l1;
            split8h(x, h0, l0);
            split8h(x + 8, h1, l1);
            char* xhp = smc + xhOff[sn] + bp_ * 80 + bkh * 32;
            char* xlp = smc + xlOff[sn] + bp_ * 80 + bkh * 32;
            *(uint4*)(xhp) = h0; *(uint4*)(xhp + 16) = h1;
            *(uint4*)(xlp) = l0; *(uint4*)(xlp + 16) = l1;
            const int wr = tid >> 2;
            const int ws = tid & 3;
            *(uint4*)(smc + whOff[sn] + wr * 80 + ws * 16) =
                *(const uint4*)(g_W1h + wr * 512 + cn * 32 + ws * 8);
        }
#pragma unroll
        for (int ks = 0; ks < 2; ks++) {
            uint32_t ah[4][4], al[4][4];
#pragma unroll
            for (int mt = 0; mt < 4; mt++) {
                uint32_t rowa = (uint32_t)(mw * 64 + mt * 16) + a_row;
                ldsm_x4(ah[mt], sbase + xhOff[s] + rowa * 80 + ks * 32 + a_colh);
                ldsm_x4(al[mt], sbase + xlOff[s] + rowa * 80 + ks * 32 + a_colh);
            }
#pragma unroll
            for (int nt = 0; nt < 4; nt++) {
                uint32_t rowb = (uint32_t)(nw * 32 + nt * 8) + b_row;
                uint32_t bh[2];
                ldsm_x2(bh, sbase + whOff[s] + rowb * 80 + ks * 32 + b_colh);
#pragma unroll
                for (int mt = 0; mt < 4; mt++) {
                    mma_f16(acc[mt][nt], ah[mt], bh[0], bh[1]);
                    mma_f16(acc[mt][nt], al[mt], bh[0], bh[1]);
                }
            }
        }
        __syncthreads();
    }

    // ---------- epilogue 1a: z1 = acc/32 + A1 + B1, gelu ----------
#pragma unroll
    for (int mt = 0; mt < 4; mt++) {
#pragma unroll
        for (int rh = 0; rh < 2; rh++) {
            int row = mw * 64 + mt * 16 + (lane >> 2) + rh * 8;
            int il = row >> 4, jl = row & 15;
#pragma unroll
            for (int nt = 0; nt < 4; nt++) {
                int colb = nw * 32 + nt * 8 + (lane & 3) * 2;
                float2 a1v = *(const float2*)&A1s[il * 132 + colb];
                float2 b1v = *(const float2*)&B1s[jl * 132 + colb];
                acc[mt][nt][rh * 2 + 0] = gelu_f(acc[mt][nt][rh * 2 + 0] * XINV + a1v.x + b1v.x);
                acc[mt][nt][rh * 2 + 1] = gelu_f(acc[mt][nt][rh * 2 + 1] * XINV + a1v.y + b1v.y);
            }
        }
    }
    __syncthreads();

    // ---------- epilogue 1b: Y*32 split to smem chunk nw ----------
#pragma unroll
    for (int mt = 0; mt < 4; mt++) {
#pragma unroll
        for (int nt = 0; nt < 4; nt++) {
#pragma unroll
            for (int rh = 0; rh < 2; rh++) {
                int row = mw * 64 + mt * 16 + (lane >> 2) + rh * 8;
                int cloc = nt * 8 + (lane & 3) * 2;
                float y0 = XSCALE * acc[mt][nt][rh * 2 + 0];
                float y1 = XSCALE * acc[mt][nt][rh * 2 + 1];
                uint32_t hp = packh(y0, y1);
                uint32_t lp2 = packh(y0 - h_lo(hp), y1 - h_hi(hp));
                *(uint32_t*)(smc + SM_YH(nw) + row * 80 + cloc * 2) = hp;
                *(uint32_t*)(smc + SM_YL(nw) + row * 80 + cloc * 2) = lp2;
            }
        }
    }
#pragma unroll
    for (int mt = 0; mt < 4; mt++)
#pragma unroll
        for (int nt = 0; nt < 4; nt++)
#pragma unroll
            for (int r = 0; r < 4; r++) acc[mt][nt][r] = 0.0f;
    __syncthreads();

    // ---------- GEMM2: K=128 in 4 chunks of 32 ----------
    for (int kc = 0; kc < 4; kc++) {
        {
            const int wr = tid >> 2;
            const int ws = tid & 3;
            *(uint4*)(smc + SM_W2H + wr * 80 + ws * 16) =
                *(const uint4*)(g_W2h + wr * 128 + kc * 32 + ws * 8);
        }
        __syncthreads();
#pragma unroll
        for (int ks = 0; ks < 2; ks++) {
            uint32_t ah[4][4], al[4][4];
#pragma unroll
            for (int mt = 0; mt < 4; mt++) {
                uint32_t rowa = (uint32_t)(mw * 64 + mt * 16) + a_row;
                ldsm_x4(ah[mt], sbase + SM_YH(kc) + rowa * 80 + ks * 32 + a_colh);
                ldsm_x4(al[mt], sbase + SM_YL(kc) + rowa * 80 + ks * 32 + a_colh);
            }
#pragma unroll
            for (int nt = 0; nt < 4; nt++) {
                uint32_t rowb = (uint32_t)(nw * 32 + nt * 8) + b_row;
                uint32_t bh[2];
                ldsm_x2(bh, sbase + SM_W2H + rowb * 80 + ks * 32 + b_colh);
#pragma unroll
                for (int mt = 0; mt < 4; mt++) {
                    mma_f16(acc[mt][nt], ah[mt], bh[0], bh[1]);
                    mma_f16(acc[mt][nt], al[mt], bh[0], bh[1]);
                }
            }
        }
        __syncthreads();
    }

    // ---------- epilogue 2: gelu + w3 dot, reduce, outputs ----------
    {
        float part[4][2];
#pragma unroll
        for (int mt = 0; mt < 4; mt++) { part[mt][0] = 0.0f; part[mt][1] = 0.0f; }
#pragma unroll
        for (int nt = 0; nt < 4; nt++) {
            int colb = nw * 32 + nt * 8 + (lane & 3) * 2;
            float w3a = __ldg(W3 + colb), w3b = __ldg(W3 + colb + 1);
            float b2a = __ldg(b2g + colb), b2b = __ldg(b2g + colb + 1);
#pragma unroll
            for (int mt = 0; mt < 4; mt++) {
                part[mt][0] += w3a * gelu_f(acc[mt][nt][0] * XINV + b2a) + w3b * gelu_f(acc[mt][nt][1] * XINV + b2b);
                part[mt][1] += w3a * gelu_f(acc[mt][nt][2] * XINV + b2a) + w3b * gelu_f(acc[mt][nt][3] * XINV + b2b);
            }
        }
#pragma unroll
        for (int off = 1; off <= 2; off <<= 1) {
#pragma unroll
            for (int mt = 0; mt < 4; mt++) {
                part[mt][0] += __shfl_xor_sync(0xFFFFFFFFu, part[mt][0], off);
                part[mt][1] += __shfl_xor_sync(0xFFFFFFFFu, part[mt][1], off);
            }
        }
        if ((lane & 3) == 0) {
            float* ZP = (float*)(smc + SM_ZP);
#pragma unroll
            for (int mt = 0; mt < 4; mt++) {
                int row0 = mw * 64 + mt * 16 + (lane >> 2);
                ZP[nw * 256 + row0]     = part[mt][0];
                ZP[nw * 256 + row0 + 8] = part[mt][1];
            }
        }
    }
    __syncthreads();
    if (tid < 256) {
        const float* ZP = (const float*)(smc + SM_ZP);
        float v = ZP[tid] + ZP[256 + tid] + ZP[512 + tid] + ZP[768 + tid] + b3[0];
        if (isnan(v)) v = 0.0f;
        else if (isinf(v)) v = (v > 0.0f) ? 20.0f : -20.0f;
        const int gi = it + (tid >> 4);
        const int gj = jt + (tid & 15);
        if (g_lmask[b * 256 + gi] || g_pmask[b * 256 + gj]) v = -20.0f;
        const int idx = 4 + (b * 65536 + gi * 256 + gj);
        out[idx] = v;
        out[idx + 262144] = 1.0f / (1.0f + expf(-v));
    }
}

// -------------------- top-k (R5, proven) --------------------
__device__ __forceinline__ int wredsum_i(int v) {
#pragma unroll
    for (int o = 16; o; o >>= 1) v += __shfl_xor_sync(0xFFFFFFFFu, v, o);
    return v;
}
__device__ __forceinline__ float wredsum_f(float v) {
#pragma unroll
    for (int o = 16; o; o >>= 1) v += __shfl_xor_sync(0xFFFFFFFFu, v, o);
    return v;
}

__global__ __launch_bounds__(1024) void topk_kernel(float* out) {
    const int b = blockIdx.x;
    const float* data = out + 4 + b * NPAIR_B;
    const int tid = threadIdx.x, lane = tid & 31, wid = tid >> 5;
    __shared__ int hist[256];
    __shared__ unsigned s_pref;
    __shared__ int s_above;
    __shared__ float sf[32], sf2[32];
    __shared__ int si[32];

    unsigned prefix = 0u;
    int above = 0;
    for (int pass = 0; pass < 4; pass++) {
        const int bpos = 24 - 8 * pass;
        if (tid < 256) hist[tid] = 0;
        __syncthreads();
        const unsigned maskHi = (pass == 0) ? 0u : (0xFFFFFFFFu << (bpos + 8));
        for (int i = tid; i < NPAIR_B; i += 1024) {
            unsigned u = __float_as_uint(data[i]);
            unsigned k = (u & 0x80000000u) ? ~u : (u | 0x80000000u);
            if (((k ^ prefix) & maskHi) == 0)
                atomicAdd(&hist[(k >> bpos) & 255], 1);
        }
        __syncthreads();
        if (tid == 0) {
            int run = 0, chosen = 0, abv = above;
            for (int x = 255; x >= 0; --x) {
                int nr = run + hist[x];
                if (above + nr >= TOPK_K) { chosen = x; abv = above + run; break; }
                run = nr;
            }
            s_pref = prefix | ((unsigned)chosen << bpos);
            s_above = abv;
        }
        __syncthreads();
        prefix = s_pref;
        above = s_above;
        __syncthreads();
    }

    unsigned ut = (prefix & 0x80000000u) ? (prefix & 0x7FFFFFFFu) : ~prefix;
    const float vT = __uint_as_float(ut);

    float s1 = 0.0f, s2 = 0.0f;
    int cg = 0;
    for (int i = tid; i < NPAIR_B; i += 1024) {
        float v = data[i];
        unsigned u = __float_as_uint(v);
        unsigned k = (u & 0x80000000u) ? ~u : (u | 0x80000000u);
        if (k > prefix) {
            float e = expf(v - vT);
            s1 += e; s2 += e * v; cg++;
        }
    }
    s1 = wredsum_f(s1);
    s2 = wredsum_f(s2);
    cg = wredsum_i(cg);
    if (lane == 0) { sf[wid] = s1; sf2[wid] = s2; si[wid] = cg; }
    __syncthreads();
    if (tid == 0) {
        float S1 = 0.0f, S2 = 0.0f;
        int CG = 0;
        for (int w = 0; w < 32; w++) { S1 += sf[w]; S2 += sf2[w]; CG += si[w]; }
        int r = TOPK_K - CG;
        S1 += (float)r;
        S2 += (float)r * vT;
        out[b] = S2 / S1;
    }
}

// ---------------------------------------------------------------------------
extern "C" void kernel_launch(void* const* d_in, const int* in_sizes, int n_in,
                              void* d_out, int out_size)
{
    const float* ltok = (const float*)d_in[0];
    const float* ptok = (const float*)d_in[1];
    const void*  lpad = d_in[2];
    const void*  ppad = d_in[3];
    const float* Wl = (const float*)d_in[4];
    const float* bl = (const float*)d_in[5];
    const float* Wp = (const float*)d_in[6];
    const float* bp = (const float*)d_in[7];
    const float* W1 = (const float*)d_in[8];
    const float* b1 = (const float*)d_in[9];
    const float* W2 = (const float*)d_in[10];
    const float* b2 = (const float*)d_in[11];
    const float* W3 = (const float*)d_in[12];
    const float* b3 = (const float*)d_in[13];
    float* out = (float*)d_out;

    detect_kernel<<<2, 256>>>((const unsigned char*)lpad, (const unsigned char*)ppad);
    mask_kernel<<<2, 1024>>>(lpad, ppad);
    wprep_kernel<<<320, 256>>>(W1, W2);
    proj_kernel<<<dim3(4, 32), 256>>>(ltok, ptok, Wl, bl, Wp, bp);
    a1b1_kernel<<<dim3(2, 32), 256>>>(W1, b1);

    cudaFuncSetAttribute(pair_kernel, cudaFuncAttributeMaxDynamicSharedMemorySize, SMEM_PAIR);
    pair_kernel<<<dim3(16, 16, 4), 512, SMEM_PAIR>>>(b2, W3, b3, out);

    topk_kernel<<<4, 1024>>>(out);
}

// round 7
// speedup vs baseline: 8.6895x; 1.2992x over previous
#include <cuda_runtime.h>
#include <cuda_fp16.h>
#include <cstdint>
#include <math.h>

// ---------------------------------------------------------------------------
// PairwiseInteractionHead B=4, L=256, D=256, H=128, TOPK=100.
// Round 7: mma.sync m16n8k16 fp16 1-pass: X, Y, W all fp16-quantized.
// Error = 3 independent ~2^-11 quantizations, measured-calibrated ~2e-4 total.
// X and Y scaled by 32 (power of 2, exact unscale) for fp16 range hygiene.
// ---------------------------------------------------------------------------

#define NB 4
#define NPAIR_B 65536
#define TOPK_K 100
#define XSCALE 32.0f
#define XINV   0.03125f

__device__ float g_lproj[NB * 256 * 256];
__device__ float g_pproj[NB * 256 * 256];
__device__ float g_A1[NB * 256 * 128];
__device__ float g_B1[NB * 256 * 128];
__device__ int   g_lmask[NB * 256];
__device__ int   g_pmask[NB * 256];
__device__ int   g_flags[2];
__device__ __half g_W1h[128 * 512];
__device__ __half g_W2h[128 * 128];

__device__ __forceinline__ float gelu_f(float x) {
    return 0.5f * x * (1.0f + erff(x * 0.70710678118654752440f));
}

// -------------------- low-level helpers --------------------
__device__ __forceinline__ uint32_t smem_u32(const void* p) {
    uint32_t a;
    asm("{ .reg .u64 t; cvta.to.shared.u64 t, %1; cvt.u32.u64 %0, t; }" : "=r"(a) : "l"(p));
    return a;
}
__device__ __forceinline__ uint32_t packh(float x0, float x1) {
    uint32_t d;
    asm("cvt.rn.f16x2.f32 %0, %1, %2;" : "=r"(d) : "f"(x1), "f"(x0));
    return d;
}
__device__ __forceinline__ void ldsm_x4(uint32_t* r, uint32_t addr) {
    asm volatile("ldmatrix.sync.aligned.m8n8.x4.shared.b16 {%0,%1,%2,%3}, [%4];"
        : "=r"(r[0]), "=r"(r[1]), "=r"(r[2]), "=r"(r[3]) : "r"(addr));
}
__device__ __forceinline__ void ldsm_x2(uint32_t* r, uint32_t addr) {
    asm volatile("ldmatrix.sync.aligned.m8n8.x2.shared.b16 {%0,%1}, [%2];"
        : "=r"(r[0]), "=r"(r[1]) : "r"(addr));
}
__device__ __forceinline__ void mma_f16(float* c, const uint32_t* a, uint32_t b0, uint32_t b1) {
    asm volatile(
        "mma.sync.aligned.m16n8k16.row.col.f32.f16.f16.f32 "
        "{%0,%1,%2,%3}, {%4,%5,%6,%7}, {%8,%9}, {%0,%1,%2,%3};"
        : "+f"(c[0]), "+f"(c[1]), "+f"(c[2]), "+f"(c[3])
        : "r"(a[0]), "r"(a[1]), "r"(a[2]), "r"(a[3]), "r"(b0), "r"(b1));
}

// -------------------- pad-dtype detection + masks (proven) --------------------
__global__ void detect_kernel(const unsigned char* lp, const unsigned char* pp) {
    __shared__ int s_nonbin, s_oddnz, s_anynz;
    const unsigned char* p = blockIdx.x ? pp : lp;
    if (threadIdx.x == 0) { s_nonbin = 0; s_oddnz = 0; s_anynz = 0; }
    __syncthreads();
    int nonbin = 0, oddnz = 0, anynz = 0;
    for (int i = threadIdx.x; i < 1024; i += blockDim.x) {
        unsigned v = p[i];
        if (v) { anynz = 1; if (v > 1u) nonbin = 1; if (i & 3) oddnz = 1; }
    }
    if (nonbin) atomicOr(&s_nonbin, 1);
    if (oddnz)  atomicOr(&s_oddnz, 1);
    if (anynz)  atomicOr(&s_anynz, 1);
    __syncthreads();
    if (threadIdx.x == 0) {
        int f;
        if (!s_anynz) f = 0;
        else if (s_nonbin) f = 2;
        else if (s_oddnz) f = 1;
        else f = 3;
        g_flags[blockIdx.x] = f;
    }
}

__global__ void mask_kernel(const void* lp, const void* pp) {
    int buf = blockIdx.x;
    const void* p = buf ? pp : lp;
    int f = g_flags[buf];
    int i = threadIdx.x;
    int m;
    if (f == 0) m = 0;
    else if (f == 1) m = (((const unsigned char*)p)[i] != 0);
    else if (f == 2) m = (((const float*)p)[i] != 0.0f);
    else m = (((const int*)p)[i] != 0);
    (buf ? g_pmask : g_lmask)[i] = m;
}

// -------------------- weight fp16 prep --------------------
__global__ void wprep_kernel(const float* __restrict__ W1, const float* __restrict__ W2) {
    int i = blockIdx.x * 256 + threadIdx.x;
    if (i < 128 * 512) {
        g_W1h[i] = __float2half_rn(W1[(i >> 9) * 1024 + 512 + (i & 511)]);
    } else {
        int j = i - 128 * 512;
        if (j < 128 * 128) g_W2h[j] = __float2half_rn(W2[j]);
    }
}

// -------------------- projection GEMM (R1, proven) --------------------
__global__ __launch_bounds__(256) void proj_kernel(
    const float* __restrict__ ltok, const float* __restrict__ ptok,
    const float* __restrict__ Wl, const float* __restrict__ bl,
    const float* __restrict__ Wp, const float* __restrict__ bp)
{
    __shared__ float As[16][68];
    __shared__ float Bs[16][68];
    const int n0 = blockIdx.x * 64;
    const int m0 = blockIdx.y * 64;
    const bool isP = (m0 >= 1024);
    const float* in   = isP ? ptok : ltok;
    const float* W    = isP ? Wp : Wl;
    const float* bias = isP ? bp : bl;
    const int mb = isP ? (m0 - 1024) : m0;
    float* outp = isP ? g_pproj : g_lproj;
    const int tid = threadIdx.x;
    const int tx = tid & 15, ty = tid >> 4;
    const int lr = tid >> 2, lc = (tid & 3) * 4;
    float acc[4][4] = {};
    for (int kt = 0; kt < 256; kt += 16) {
        float4 a4 = *(const float4*)&in[(mb + lr) * 256 + kt + lc];
        float4 b4 = *(const float4*)&W[(n0 + lr) * 256 + kt + lc];
        As[lc + 0][lr] = a4.x; As[lc + 1][lr] = a4.y; As[lc + 2][lr] = a4.z; As[lc + 3][lr] = a4.w;
        Bs[lc + 0][lr] = b4.x; Bs[lc + 1][lr] = b4.y; Bs[lc + 2][lr] = b4.z; Bs[lc + 3][lr] = b4.w;
        __syncthreads();
#pragma unroll
        for (int e = 0; e < 16; e++) {
            float4 av = *(const float4*)&As[e][ty * 4];
            float4 bv = *(const float4*)&Bs[e][tx * 4];
            acc[0][0] += av.x * bv.x; acc[0][1] += av.x * bv.y; acc[0][2] += av.x * bv.z; acc[0][3] += av.x * bv.w;
            acc[1][0] += av.y * bv.x; acc[1][1] += av.y * bv.y; acc[1][2] += av.y * bv.z; acc[1][3] += av.y * bv.w;
            acc[2][0] += av.z * bv.x; acc[2][1] += av.z * bv.y; acc[2][2] += av.z * bv.z; acc[2][3] += av.z * bv.w;
            acc[3][0] += av.w * bv.x; acc[3][1] += av.w * bv.y; acc[3][2] += av.w * bv.z; acc[3][3] += av.w * bv.w;
        }
        __syncthreads();
    }
#pragma unroll
    for (int ii = 0; ii < 4; ii++)
#pragma unroll
        for (int jj = 0; jj < 4; jj++) {
            int n = n0 + tx * 4 + jj;
            outp[(mb + ty * 4 + ii) * 256 + n] = acc[ii][jj] + bias[n];
        }
}

// -------------------- A1/B1 GEMM (R1, proven) --------------------
__global__ __launch_bounds__(256) void a1b1_kernel(
    const float* __restrict__ W1, const float* __restrict__ b1)
{
    __shared__ float As[16][68];
    __shared__ float Bs[16][68];
    const int n0 = blockIdx.x * 64;
    const int m0 = blockIdx.y * 64;
    const bool isP = (m0 >= 1024);
    const float* in = isP ? g_pproj : g_lproj;
    const int mb = isP ? (m0 - 1024) : m0;
    const int colOff = isP ? 256 : 0;
    float* outp = isP ? g_B1 : g_A1;
    const int tid = threadIdx.x;
    const int tx = tid & 15, ty = tid >> 4;
    const int lr = tid >> 2, lc = (tid & 3) * 4;
    float acc[4][4] = {};
    for (int kt = 0; kt < 256; kt += 16) {
        float4 a4 = *(const float4*)&in[(mb + lr) * 256 + kt + lc];
        float4 b4 = *(const float4*)&W1[(n0 + lr) * 1024 + colOff + kt + lc];
        As[lc + 0][lr] = a4.x; As[lc + 1][lr] = a4.y; As[lc + 2][lr] = a4.z; As[lc + 3][lr] = a4.w;
        Bs[lc + 0][lr] = b4.x; Bs[lc + 1][lr] = b4.y; Bs[lc + 2][lr] = b4.z; Bs[lc + 3][lr] = b4.w;
        __syncthreads();
#pragma unroll
        for (int e = 0; e < 16; e++) {
            float4 av = *(const float4*)&As[e][ty * 4];
            float4 bv = *(const float4*)&Bs[e][tx * 4];
            acc[0][0] += av.x * bv.x; acc[0][1] += av.x * bv.y; acc[0][2] += av.x * bv.z; acc[0][3] += av.x * bv.w;
            acc[1][0] += av.y * bv.x; acc[1][1] += av.y * bv.y; acc[1][2] += av.y * bv.z; acc[1][3] += av.y * bv.w;
            acc[2][0] += av.z * bv.x; acc[2][1] += av.z * bv.y; acc[2][2] += av.z * bv.z; acc[2][3] += av.z * bv.w;
            acc[3][0] += av.w * bv.x; acc[3][1] += av.w * bv.y; acc[3][2] += av.w * bv.z; acc[3][3] += av.w * bv.w;
        }
        __syncthreads();
    }
#pragma unroll
    for (int ii = 0; ii < 4; ii++)
#pragma unroll
        for (int jj = 0; jj < 4; jj++) {
            int n = n0 + tx * 4 + jj;
            float bv = isP ? 0.0f : b1[n];
            outp[(mb + ty * 4 + ii) * 128 + n] = acc[ii][jj] + bv;
        }
}

// -------------------- tensor-core pair kernel (fp16 1-pass) --------------------
// 512 threads = 16 warps, 4(m)x4(n); warp tile 64 pairs x 32 h.
// smem byte offsets (phase 1):
#define SM_LS    0u        // [16][260] f32
#define SM_PS    16640u
#define SM_XH0   33280u    // [256][80B]
#define SM_XH1   53760u
#define SM_WH0   74240u    // [128][80B]
#define SM_WH1   84480u
#define SM_A1    94720u    // [16][132] f32
#define SM_B1    103168u   // ends 111616
// phase-2 aliases (written only after phase-1 regions are dead):
#define SM_YH(c)  ((c) * 20480u)   // 4 chunks [256][80B], ends 81920
#define SM_W2H    81920u           // [128][80B] -> 92160
#define SM_ZP     92160u           // [4][256] f32 -> 96256
#define SMEM_PAIR 111616

__global__ __launch_bounds__(512, 1) void pair_kernel(
    const float* __restrict__ b2g, const float* __restrict__ W3,
    const float* __restrict__ b3, float* __restrict__ out)
{
    extern __shared__ char smc[];
    float* Ls  = (float*)(smc + SM_LS);
    float* Ps  = (float*)(smc + SM_PS);
    float* A1s = (float*)(smc + SM_A1);
    float* B1s = (float*)(smc + SM_B1);
    const uint32_t sbase = smem_u32(smc);

    const int tid  = threadIdx.x;
    const int lane = tid & 31;
    const int wid  = tid >> 5;
    const int mw   = wid & 3;
    const int nw   = wid >> 2;
    const int b  = blockIdx.z;
    const int it = blockIdx.y * 16;
    const int jt = blockIdx.x * 16;

    const uint32_t xhOff[2] = {SM_XH0, SM_XH1};
    const uint32_t whOff[2] = {SM_WH0, SM_WH1};

    const uint32_t a_row  = (lane & 7) + ((lane >> 3) & 1) * 8;
    const uint32_t a_colh = ((lane >> 4) & 1) * 16;
    const uint32_t b_row  = lane & 7;
    const uint32_t b_colh = ((lane >> 3) & 1) * 16;

    // ---- prologue loads ----
    {
        const float* lsrc = g_lproj + (size_t)(b * 256 + it) * 256;
        const float* psrc = g_pproj + (size_t)(b * 256 + jt) * 256;
#pragma unroll
        for (int q = 0; q < 2; q++) {
            int idx = q * 512 + tid;
            int r = idx >> 6;
            int c = (idx & 63) * 4;
            *(float4*)&Ls[r * 260 + c] = *(const float4*)&lsrc[r * 256 + c];
            *(float4*)&Ps[r * 260 + c] = *(const float4*)&psrc[r * 256 + c];
        }
        const float* a1src = g_A1 + (size_t)(b * 256 + it) * 128;
        const float* b1src = g_B1 + (size_t)(b * 256 + jt) * 128;
        int r = tid >> 5;
        int c = (tid & 31) * 4;
        *(float4*)&A1s[r * 132 + c] = *(const float4*)&a1src[r * 128 + c];
        *(float4*)&B1s[r * 132 + c] = *(const float4*)&b1src[r * 128 + c];
    }

    float acc[4][4][4];
#pragma unroll
    for (int mt = 0; mt < 4; mt++)
#pragma unroll
        for (int nt = 0; nt < 4; nt++)
#pragma unroll
            for (int r = 0; r < 4; r++) acc[mt][nt][r] = 0.0f;

    const int bp_ = tid & 255;
    const int bkh = tid >> 8;
    const float* blrow = Ls + (bp_ >> 4) * 260;
    const float* bprow = Ps + (bp_ & 15) * 260;

    // ---------- GEMM1: 16 K-chunks of 32 ----------
    __syncthreads();
    {
        const int kcol = bkh * 16;
        uint32_t xp[8];
#pragma unroll
        for (int q = 0; q < 16; q += 4) {
            float4 lv = *(const float4*)(blrow + kcol + q);
            float4 pv = *(const float4*)(bprow + kcol + q);
            xp[q / 2]     = packh(XSCALE * (lv.x * pv.x), XSCALE * (lv.y * pv.y));
            xp[q / 2 + 1] = packh(XSCALE * (lv.z * pv.z), XSCALE * (lv.w * pv.w));
        }
        char* xhp = smc + SM_XH0 + bp_ * 80 + bkh * 32;
        *(uint4*)(xhp)      = make_uint4(xp[0], xp[1], xp[2], xp[3]);
        *(uint4*)(xhp + 16) = make_uint4(xp[4], xp[5], xp[6], xp[7]);
        const int wr = tid >> 2;
        const int ws = tid & 3;
        *(uint4*)(smc + SM_WH0 + wr * 80 + ws * 16) = *(const uint4*)(g_W1h + wr * 512 + ws * 8);
    }
    __syncthreads();

    for (int c = 0; c < 16; c++) {
        const int s = c & 1;
        if (c + 1 < 16) {
            const int cn = c + 1;
            const int sn = cn & 1;
            const bool mul = (cn < 8);
            const int kb = (mul ? cn * 32 : (cn - 8) * 32) + bkh * 16;
            uint32_t xp[8];
#pragma unroll
            for (int q = 0; q < 16; q += 4) {
                float4 lv = *(const float4*)(blrow + kb + q);
                float4 pv = *(const float4*)(bprow + kb + q);
                float x0, x1, x2, x3;
                if (mul) {
                    x0 = XSCALE * (lv.x * pv.x); x1 = XSCALE * (lv.y * pv.y);
                    x2 = XSCALE * (lv.z * pv.z); x3 = XSCALE * (lv.w * pv.w);
                } else {
                    x0 = XSCALE * fabsf(lv.x - pv.x); x1 = XSCALE * fabsf(lv.y - pv.y);
                    x2 = XSCALE * fabsf(lv.z - pv.z); x3 = XSCALE * fabsf(lv.w - pv.w);
                }
                xp[q / 2]     = packh(x0, x1);
                xp[q / 2 + 1] = packh(x2, x3);
            }
            char* xhp = smc + xhOff[sn] + bp_ * 80 + bkh * 32;
            *(uint4*)(xhp)      = make_uint4(xp[0], xp[1], xp[2], xp[3]);
            *(uint4*)(xhp + 16) = make_uint4(xp[4], xp[5], xp[6], xp[7]);
            const int wr = tid >> 2;
            const int ws = tid & 3;
            *(uint4*)(smc + whOff[sn] + wr * 80 + ws * 16) =
                *(const uint4*)(g_W1h + wr * 512 + cn * 32 + ws * 8);
        }
#pragma unroll
        for (int ks = 0; ks < 2; ks++) {
            uint32_t ah[4][4];
#pragma unroll
            for (int mt = 0; mt < 4; mt++) {
                uint32_t rowa = (uint32_t)(mw * 64 + mt * 16) + a_row;
                ldsm_x4(ah[mt], sbase + xhOff[s] + rowa * 80 + ks * 32 + a_colh);
            }
#pragma unroll
            for (int nt = 0; nt < 4; nt++) {
                uint32_t rowb = (uint32_t)(nw * 32 + nt * 8) + b_row;
                uint32_t bh[2];
                ldsm_x2(bh, sbase + whOff[s] + rowb * 80 + ks * 32 + b_colh);
#pragma unroll
                for (int mt = 0; mt < 4; mt++)
                    mma_f16(acc[mt][nt], ah[mt], bh[0], bh[1]);
            }
        }
        __syncthreads();
    }

    // ---------- epilogue 1a: z1 = acc/32 + A1 + B1, gelu ----------
#pragma unroll
    for (int mt = 0; mt < 4; mt++) {
#pragma unroll
        for (int rh = 0; rh < 2; rh++) {
            int row = mw * 64 + mt * 16 + (lane >> 2) + rh * 8;
            int il = row >> 4, jl = row & 15;
#pragma unroll
            for (int nt = 0; nt < 4; nt++) {
                int colb = nw * 32 + nt * 8 + (lane & 3) * 2;
                float2 a1v = *(const float2*)&A1s[il * 132 + colb];
                float2 b1v = *(const float2*)&B1s[jl * 132 + colb];
                acc[mt][nt][rh * 2 + 0] = gelu_f(acc[mt][nt][rh * 2 + 0] * XINV + a1v.x + b1v.x);
                acc[mt][nt][rh * 2 + 1] = gelu_f(acc[mt][nt][rh * 2 + 1] * XINV + a1v.y + b1v.y);
            }
        }
    }
    __syncthreads();   // phase-1 smem dead; Y region safe

    // ---------- epilogue 1b: Y*32 fp16 to smem chunk nw ----------
#pragma unroll
    for (int mt = 0; mt < 4; mt++) {
#pragma unroll
        for (int nt = 0; nt < 4; nt++) {
#pragma unroll
            for (int rh = 0; rh < 2; rh++) {
                int row = mw * 64 + mt * 16 + (lane >> 2) + rh * 8;
                int cloc = nt * 8 + (lane & 3) * 2;
                uint32_t hp = packh(XSCALE * acc[mt][nt][rh * 2 + 0],
                                    XSCALE * acc[mt][nt][rh * 2 + 1]);
                *(uint32_t*)(smc + SM_YH(nw) + row * 80 + cloc * 2) = hp;
            }
        }
    }
#pragma unroll
    for (int mt = 0; mt < 4; mt++)
#pragma unroll
        for (int nt = 0; nt < 4; nt++)
#pragma unroll
            for (int r = 0; r < 4; r++) acc[mt][nt][r] = 0.0f;
    __syncthreads();

    // ---------- GEMM2: K=128 in 4 chunks of 32 ----------
    for (int kc = 0; kc < 4; kc++) {
        {
            const int wr = tid >> 2;
            const int ws = tid & 3;
            *(uint4*)(smc + SM_W2H + wr * 80 + ws * 16) =
                *(const uint4*)(g_W2h + wr * 128 + kc * 32 + ws * 8);
        }
        __syncthreads();
#pragma unroll
        for (int ks = 0; ks < 2; ks++) {
            uint32_t ah[4][4];
#pragma unroll
            for (int mt = 0; mt < 4; mt++) {
                uint32_t rowa = (uint32_t)(mw * 64 + mt * 16) + a_row;
                ldsm_x4(ah[mt], sbase + SM_YH(kc) + rowa * 80 + ks * 32 + a_colh);
            }
#pragma unroll
            for (int nt = 0; nt < 4; nt++) {
                uint32_t rowb = (uint32_t)(nw * 32 + nt * 8) + b_row;
                uint32_t bh[2];
                ldsm_x2(bh, sbase + SM_W2H + rowb * 80 + ks * 32 + b_colh);
#pragma unroll
                for (int mt = 0; mt < 4; mt++)
                    mma_f16(acc[mt][nt], ah[mt], bh[0], bh[1]);
            }
        }
        __syncthreads();
    }

    // ---------- epilogue 2: gelu + w3 dot, reduce, outputs ----------
    {
        float part[4][2];
#pragma unroll
        for (int mt = 0; mt < 4; mt++) { part[mt][0] = 0.0f; part[mt][1] = 0.0f; }
#pragma unroll
        for (int nt = 0; nt < 4; nt++) {
            int colb = nw * 32 + nt * 8 + (lane & 3) * 2;
            float w3a = __ldg(W3 + colb), w3b = __ldg(W3 + colb + 1);
            float b2a = __ldg(b2g + colb), b2b = __ldg(b2g + colb + 1);
#pragma unroll
            for (int mt = 0; mt < 4; mt++) {
                part[mt][0] += w3a * gelu_f(acc[mt][nt][0] * XINV + b2a) + w3b * gelu_f(acc[mt][nt][1] * XINV + b2b);
                part[mt][1] += w3a * gelu_f(acc[mt][nt][2] * XINV + b2a) + w3b * gelu_f(acc[mt][nt][3] * XINV + b2b);
            }
        }
#pragma unroll
        for (int off = 1; off <= 2; off <<= 1) {
#pragma unroll
            for (int mt = 0; mt < 4; mt++) {
                part[mt][0] += __shfl_xor_sync(0xFFFFFFFFu, part[mt][0], off);
                part[mt][1] += __shfl_xor_sync(0xFFFFFFFFu, part[mt][1], off);
            }
        }
        if ((lane & 3) == 0) {
            float* ZP = (float*)(smc + SM_ZP);
#pragma unroll
            for (int mt = 0; mt < 4; mt++) {
                int row0 = mw * 64 + mt * 16 + (lane >> 2);
                ZP[nw * 256 + row0]     = part[mt][0];
                ZP[nw * 256 + row0 + 8] = part[mt][1];
            }
        }
    }
    __syncthreads();
    if (tid < 256) {
        const float* ZP = (const float*)(smc + SM_ZP);
        float v = ZP[tid] + ZP[256 + tid] + ZP[512 + tid] + ZP[768 + tid] + b3[0];
        if (isnan(v)) v = 0.0f;
        else if (isinf(v)) v = (v > 0.0f) ? 20.0f : -20.0f;
        const int gi = it + (tid >> 4);
        const int gj = jt + (tid & 15);
        if (g_lmask[b * 256 + gi] || g_pmask[b * 256 + gj]) v = -20.0f;
        const int idx = 4 + (b * 65536 + gi * 256 + gj);
        out[idx] = v;
        out[idx + 262144] = 1.0f / (1.0f + expf(-v));
    }
}

// -------------------- top-k (R5, proven) --------------------
__device__ __forceinline__ int wredsum_i(int v) {
#pragma unroll
    for (int o = 16; o; o >>= 1) v += __shfl_xor_sync(0xFFFFFFFFu, v, o);
    return v;
}
__device__ __forceinline__ float wredsum_f(float v) {
#pragma unroll
    for (int o = 16; o; o >>= 1) v += __shfl_xor_sync(0xFFFFFFFFu, v, o);
    return v;
}

__global__ __launch_bounds__(1024) void topk_kernel(float* out) {
    const int b = blockIdx.x;
    const float* data = out + 4 + b * NPAIR_B;
    const int tid = threadIdx.x, lane = tid & 31, wid = tid >> 5;
    __shared__ int hist[256];
    __shared__ unsigned s_pref;
    __shared__ int s_above;
    __shared__ float sf[32], sf2[32];
    __shared__ int si[32];

    unsigned prefix = 0u;
    int above = 0;
    for (int pass = 0; pass < 4; pass++) {
        const int bpos = 24 - 8 * pass;
        if (tid < 256) hist[tid] = 0;
        __syncthreads();
        const unsigned maskHi = (pass == 0) ? 0u : (0xFFFFFFFFu << (bpos + 8));
        for (int i = tid; i < NPAIR_B; i += 1024) {
            unsigned u = __float_as_uint(data[i]);
            unsigned k = (u & 0x80000000u) ? ~u : (u | 0x80000000u);
            if (((k ^ prefix) & maskHi) == 0)
                atomicAdd(&hist[(k >> bpos) & 255], 1);
        }
        __syncthreads();
        if (tid == 0) {
            int run = 0, chosen = 0, abv = above;
            for (int x = 255; x >= 0; --x) {
                int nr = run + hist[x];
                if (above + nr >= TOPK_K) { chosen = x; abv = above + run; break; }
                run = nr;
            }
            s_pref = prefix | ((unsigned)chosen << bpos);
            s_above = abv;
        }
        __syncthreads();
        prefix = s_pref;
        above = s_above;
        __syncthreads();
    }

    unsigned ut = (prefix & 0x80000000u) ? (prefix & 0x7FFFFFFFu) : ~prefix;
    const float vT = __uint_as_float(ut);

    float s1 = 0.0f, s2 = 0.0f;
    int cg = 0;
    for (int i = tid; i < NPAIR_B; i += 1024) {
        float v = data[i];
        unsigned u = __float_as_uint(v);
        unsigned k = (u & 0x80000000u) ? ~u : (u | 0x80000000u);
        if (k > prefix) {
            float e = expf(v - vT);
            s1 += e; s2 += e * v; cg++;
        }
    }
    s1 = wredsum_f(s1);
    s2 = wredsum_f(s2);
    cg = wredsum_i(cg);
    if (lane == 0) { sf[wid] = s1; sf2[wid] = s2; si[wid] = cg; }
    __syncthreads();
    if (tid == 0) {
        float S1 = 0.0f, S2 = 0.0f;
        int CG = 0;
        for (int w = 0; w < 32; w++) { S1 += sf[w]; S2 += sf2[w]; CG += si[w]; }
        int r = TOPK_K - CG;
        S1 += (float)r;
        S2 += (float)r * vT;
        out[b] = S2 / S1;
    }
}

// ---------------------------------------------------------------------------
extern "C" void kernel_launch(void* const* d_in, const int* in_sizes, int n_in,
                              void* d_out, int out_size)
{
    const float* ltok = (const float*)d_in[0];
    const float* ptok = (const float*)d_in[1];
    const void*  lpad = d_in[2];
    const void*  ppad = d_in[3];
    const float* Wl = (const float*)d_in[4];
    const float* bl = (const float*)d_in[5];
    const float* Wp = (const float*)d_in[6];
    const float* bp = (const float*)d_in[7];
    const float* W1 = (const float*)d_in[8];
    const float* b1 = (const float*)d_in[9];
    const float* W2 = (const float*)d_in[10];
    const float* b2 = (const float*)d_in[11];
    const float* W3 = (const float*)d_in[12];
    const float* b3 = (const float*)d_in[13];
    float* out = (float*)d_out;

    detect_kernel<<<2, 256>>>((const unsigned char*)lpad, (const unsigned char*)ppad);
    mask_kernel<<<2, 1024>>>(lpad, ppad);
    wprep_kernel<<<320, 256>>>(W1, W2);
    proj_kernel<<<dim3(4, 32), 256>>>(ltok, ptok, Wl, bl, Wp, bp);
    a1b1_kernel<<<dim3(2, 32), 256>>>(W1, b1);

    cudaFuncSetAttribute(pair_kernel, cudaFuncAttributeMaxDynamicSharedMemorySize, SMEM_PAIR);
    pair_kernel<<<dim3(16, 16, 4), 512, SMEM_PAIR>>>(b2, W3, b3, out);

    topk_kernel<<<4, 1024>>>(out);
}

// round 8
// speedup vs baseline: 8.7014x; 1.0014x over previous
#include <cuda_runtime.h>
#include <cuda_fp16.h>
#include <cstdint>
#include <math.h>

// ---------------------------------------------------------------------------
// PairwiseInteractionHead B=4, L=256, D=256, H=128, TOPK=100.
// Round 7: mma.sync m16n8k16 fp16 1-pass: X, Y, W all fp16-quantized.
// Error = 3 independent ~2^-11 quantizations, measured-calibrated ~2e-4 total.
// X and Y scaled by 32 (power of 2, exact unscale) for fp16 range hygiene.
// ---------------------------------------------------------------------------

#define NB 4
#define NPAIR_B 65536
#define TOPK_K 100
#define XSCALE 32.0f
#define XINV   0.03125f

__device__ float g_lproj[NB * 256 * 256];
__device__ float g_pproj[NB * 256 * 256];
__device__ float g_A1[NB * 256 * 128];
__device__ float g_B1[NB * 256 * 128];
__device__ int   g_lmask[NB * 256];
__device__ int   g_pmask[NB * 256];
__device__ int   g_flags[2];
__device__ __half g_W1h[128 * 512];
__device__ __half g_W2h[128 * 128];

__device__ __forceinline__ float gelu_f(float x) {
    return 0.5f * x * (1.0f + erff(x * 0.70710678118654752440f));
}

// -------------------- low-level helpers --------------------
__device__ __forceinline__ uint32_t smem_u32(const void* p) {
    uint32_t a;
    asm("{ .reg .u64 t; cvta.to.shared.u64 t, %1; cvt.u32.u64 %0, t; }" : "=r"(a) : "l"(p));
    return a;
}
__device__ __forceinline__ uint32_t packh(float x0, float x1) {
    uint32_t d;
    asm("cvt.rn.f16x2.f32 %0, %1, %2;" : "=r"(d) : "f"(x1), "f"(x0));
    return d;
}
__device__ __forceinline__ void ldsm_x4(uint32_t* r, uint32_t addr) {
    asm volatile("ldmatrix.sync.aligned.m8n8.x4.shared.b16 {%0,%1,%2,%3}, [%4];"
        : "=r"(r[0]), "=r"(r[1]), "=r"(r[2]), "=r"(r[3]) : "r"(addr));
}
__device__ __forceinline__ void ldsm_x2(uint32_t* r, uint32_t addr) {
    asm volatile("ldmatrix.sync.aligned.m8n8.x2.shared.b16 {%0,%1}, [%2];"
        : "=r"(r[0]), "=r"(r[1]) : "r"(addr));
}
__device__ __forceinline__ void mma_f16(float* c, const uint32_t* a, uint32_t b0, uint32_t b1) {
    asm volatile(
        "mma.sync.aligned.m16n8k16.row.col.f32.f16.f16.f32 "
        "{%0,%1,%2,%3}, {%4,%5,%6,%7}, {%8,%9}, {%0,%1,%2,%3};"
        : "+f"(c[0]), "+f"(c[1]), "+f"(c[2]), "+f"(c[3])
        : "r"(a[0]), "r"(a[1]), "r"(a[2]), "r"(a[3]), "r"(b0), "r"(b1));
}

// -------------------- pad-dtype detection + masks (proven) --------------------
__global__ void detect_kernel(const unsigned char* lp, const unsigned char* pp) {
    __shared__ int s_nonbin, s_oddnz, s_anynz;
    const unsigned char* p = blockIdx.x ? pp : lp;
    if (threadIdx.x == 0) { s_nonbin = 0; s_oddnz = 0; s_anynz = 0; }
    __syncthreads();
    int nonbin = 0, oddnz = 0, anynz = 0;
    for (int i = threadIdx.x; i < 1024; i += blockDim.x) {
        unsigned v = p[i];
        if (v) { anynz = 1; if (v > 1u) nonbin = 1; if (i & 3) oddnz = 1; }
    }
    if (nonbin) atomicOr(&s_nonbin, 1);
    if (oddnz)  atomicOr(&s_oddnz, 1);
    if (anynz)  atomicOr(&s_anynz, 1);
    __syncthreads();
    if (threadIdx.x == 0) {
        int f;
        if (!s_anynz) f = 0;
        else if (s_nonbin) f = 2;
        else if (s_oddnz) f = 1;
        else f = 3;
        g_flags[blockIdx.x] = f;
    }
}

__global__ void mask_kernel(const void* lp, const void* pp) {
    int buf = blockIdx.x;
    const void* p = buf ? pp : lp;
    int f = g_flags[buf];
    int i = threadIdx.x;
    int m;
    if (f == 0) m = 0;
    else if (f == 1) m = (((const unsigned char*)p)[i] != 0);
    else if (f == 2) m = (((const float*)p)[i] != 0.0f);
    else m = (((const int*)p)[i] != 0);
    (buf ? g_pmask : g_lmask)[i] = m;
}

// -------------------- weight fp16 prep --------------------
__global__ void wprep_kernel(const float* __restrict__ W1, const float* __restrict__ W2) {
    int i = blockIdx.x * 256 + threadIdx.x;
    if (i < 128 * 512) {
        g_W1h[i] = __float2half_rn(W1[(i >> 9) * 1024 + 512 + (i & 511)]);
    } else {
        int j = i - 128 * 512;
        if (j < 128 * 128) g_W2h[j] = __float2half_rn(W2[j]);
    }
}

// -------------------- projection GEMM (R1, proven) --------------------
__global__ __launch_bounds__(256) void proj_kernel(
    const float* __restrict__ ltok, const float* __restrict__ ptok,
    const float* __restrict__ Wl, const float* __restrict__ bl,
    const float* __restrict__ Wp, const float* __restrict__ bp)
{
    __shared__ float As[16][68];
    __shared__ float Bs[16][68];
    const int n0 = blockIdx.x * 64;
    const int m0 = blockIdx.y * 64;
    const bool isP = (m0 >= 1024);
    const float* in   = isP ? ptok : ltok;
    const float* W    = isP ? Wp : Wl;
    const float* bias = isP ? bp : bl;
    const int mb = isP ? (m0 - 1024) : m0;
    float* outp = isP ? g_pproj : g_lproj;
    const int tid = threadIdx.x;
    const int tx = tid & 15, ty = tid >> 4;
    const int lr = tid >> 2, lc = (tid & 3) * 4;
    float acc[4][4] = {};
    for (int kt = 0; kt < 256; kt += 16) {
        float4 a4 = *(const float4*)&in[(mb + lr) * 256 + kt + lc];
        float4 b4 = *(const float4*)&W[(n0 + lr) * 256 + kt + lc];
        As[lc + 0][lr] = a4.x; As[lc + 1][lr] = a4.y; As[lc + 2][lr] = a4.z; As[lc + 3][lr] = a4.w;
        Bs[lc + 0][lr] = b4.x; Bs[lc + 1][lr] = b4.y; Bs[lc + 2][lr] = b4.z; Bs[lc + 3][lr] = b4.w;
        __syncthreads();
#pragma unroll
        for (int e = 0; e < 16; e++) {
            float4 av = *(const float4*)&As[e][ty * 4];
            float4 bv = *(const float4*)&Bs[e][tx * 4];
            acc[0][0] += av.x * bv.x; acc[0][1] += av.x * bv.y; acc[0][2] += av.x * bv.z; acc[0][3] += av.x * bv.w;
            acc[1][0] += av.y * bv.x; acc[1][1] += av.y * bv.y; acc[1][2] += av.y * bv.z; acc[1][3] += av.y * bv.w;
            acc[2][0] += av.z * bv.x; acc[2][1] += av.z * bv.y; acc[2][2] += av.z * bv.z; acc[2][3] += av.z * bv.w;
            acc[3][0] += av.w * bv.x; acc[3][1] += av.w * bv.y; acc[3][2] += av.w * bv.z; acc[3][3] += av.w * bv.w;
        }
        __syncthreads();
    }
#pragma unroll
    for (int ii = 0; ii < 4; ii++)
#pragma unroll
        for (int jj = 0; jj < 4; jj++) {
            int n = n0 + tx * 4 + jj;
            outp[(mb + ty * 4 + ii) * 256 + n] = acc[ii][jj] + bias[n];
        }
}

// -------------------- A1/B1 GEMM (R1, proven) --------------------
__global__ __launch_bounds__(256) void a1b1_kernel(
    const float* __restrict__ W1, const float* __restrict__ b1)
{
    __shared__ float As[16][68];
    __shared__ float Bs[16][68];
    const int n0 = blockIdx.x * 64;
    const int m0 = blockIdx.y * 64;
    const bool isP = (m0 >= 1024);
    const float* in = isP ? g_pproj : g_lproj;
    const int mb = isP ? (m0 - 1024) : m0;
    const int colOff = isP ? 256 : 0;
    float* outp = isP ? g_B1 : g_A1;
    const int tid = threadIdx.x;
    const int tx = tid & 15, ty = tid >> 4;
    const int lr = tid >> 2, lc = (tid & 3) * 4;
    float acc[4][4] = {};
    for (int kt = 0; kt < 256; kt += 16) {
        float4 a4 = *(const float4*)&in[(mb + lr) * 256 + kt + lc];
        float4 b4 = *(const float4*)&W1[(n0 + lr) * 1024 + colOff + kt + lc];
        As[lc + 0][lr] = a4.x; As[lc + 1][lr] = a4.y; As[lc + 2][lr] = a4.z; As[lc + 3][lr] = a4.w;
        Bs[lc + 0][lr] = b4.x; Bs[lc + 1][lr] = b4.y; Bs[lc + 2][lr] = b4.z; Bs[lc + 3][lr] = b4.w;
        __syncthreads();
#pragma unroll
        for (int e = 0; e < 16; e++) {
            float4 av = *(const float4*)&As[e][ty * 4];
            float4 bv = *(const float4*)&Bs[e][tx * 4];
            acc[0][0] += av.x * bv.x; acc[0][1] += av.x * bv.y; acc[0][2] += av.x * bv.z; acc[0][3] += av.x * bv.w;
            acc[1][0] += av.y * bv.x; acc[1][1] += av.y * bv.y; acc[1][2] += av.y * bv.z; acc[1][3] += av.y * bv.w;
            acc[2][0] += av.z * bv.x; acc[2][1] += av.z * bv.y; acc[2][2] += av.z * bv.z; acc[2][3] += av.z * bv.w;
            acc[3][0] += av.w * bv.x; acc[3][1] += av.w * bv.y; acc[3][2] += av.w * bv.z; acc[3][3] += av.w * bv.w;
        }
        __syncthreads();
    }
#pragma unroll
    for (int ii = 0; ii < 4; ii++)
#pragma unroll
        for (int jj = 0; jj < 4; jj++) {
            int n = n0 + tx * 4 + jj;
            float bv = isP ? 0.0f : b1[n];
            outp[(mb + ty * 4 + ii) * 128 + n] = acc[ii][jj] + bv;
        }
}

// -------------------- tensor-core pair kernel (fp16 1-pass) --------------------
// 512 threads = 16 warps, 4(m)x4(n); warp tile 64 pairs x 32 h.
// smem byte offsets (phase 1):
#define SM_LS    0u        // [16][260] f32
#define SM_PS    16640u
#define SM_XH0   33280u    // [256][80B]
#define SM_XH1   53760u
#define SM_WH0   74240u    // [128][80B]
#define SM_WH1   84480u
#define SM_A1    94720u    // [16][132] f32
#define SM_B1    103168u   // ends 111616
// phase-2 aliases (written only after phase-1 regions are dead):
#define SM_YH(c)  ((c) * 20480u)   // 4 chunks [256][80B], ends 81920
#define SM_W2H    81920u           // [128][80B] -> 92160
#define SM_ZP     92160u           // [4][256] f32 -> 96256
#define SMEM_PAIR 111616

__global__ __launch_bounds__(512, 1) void pair_kernel(
    const float* __restrict__ b2g, const float* __restrict__ W3,
    const float* __restrict__ b3, float* __restrict__ out)
{
    extern __shared__ char smc[];
    float* Ls  = (float*)(smc + SM_LS);
    float* Ps  = (float*)(smc + SM_PS);
    float* A1s = (float*)(smc + SM_A1);
    float* B1s = (float*)(smc + SM_B1);
    const uint32_t sbase = smem_u32(smc);

    const int tid  = threadIdx.x;
    const int lane = tid & 31;
    const int wid  = tid >> 5;
    const int mw   = wid & 3;
    const int nw   = wid >> 2;
    const int b  = blockIdx.z;
    const int it = blockIdx.y * 16;
    const int jt = blockIdx.x * 16;

    const uint32_t xhOff[2] = {SM_XH0, SM_XH1};
    const uint32_t whOff[2] = {SM_WH0, SM_WH1};

    const uint32_t a_row  = (lane & 7) + ((lane >> 3) & 1) * 8;
    const uint32_t a_colh = ((lane >> 4) & 1) * 16;
    const uint32_t b_row  = lane & 7;
    const uint32_t b_colh = ((lane >> 3) & 1) * 16;

    // ---- prologue loads ----
    {
        const float* lsrc = g_lproj + (size_t)(b * 256 + it) * 256;
        const float* psrc = g_pproj + (size_t)(b * 256 + jt) * 256;
#pragma unroll
        for (int q = 0; q < 2; q++) {
            int idx = q * 512 + tid;
            int r = idx >> 6;
            int c = (idx & 63) * 4;
            *(float4*)&Ls[r * 260 + c] = *(const float4*)&lsrc[r * 256 + c];
            *(float4*)&Ps[r * 260 + c] = *(const float4*)&psrc[r * 256 + c];
        }
        const float* a1src = g_A1 + (size_t)(b * 256 + it) * 128;
        const float* b1src = g_B1 + (size_t)(b * 256 + jt) * 128;
        int r = tid >> 5;
        int c = (tid & 31) * 4;
        *(float4*)&A1s[r * 132 + c] = *(const float4*)&a1src[r * 128 + c];
        *(float4*)&B1s[r * 132 + c] = *(const float4*)&b1src[r * 128 + c];
    }

    float acc[4][4][4];
#pragma unroll
    for (int mt = 0; mt < 4; mt++)
#pragma unroll
        for (int nt = 0; nt < 4; nt++)
#pragma unroll
            for (int r = 0; r < 4; r++) acc[mt][nt][r] = 0.0f;

    const int bp_ = tid & 255;
    const int bkh = tid >> 8;
    const float* blrow = Ls + (bp_ >> 4) * 260;
    const float* bprow = Ps + (bp_ & 15) * 260;

    // ---------- GEMM1: 16 K-chunks of 32 ----------
    __syncthreads();
    {
        const int kcol = bkh * 16;
        uint32_t xp[8];
#pragma unroll
        for (int q = 0; q < 16; q += 4) {
            float4 lv = *(const float4*)(blrow + kcol + q);
            float4 pv = *(const float4*)(bprow + kcol + q);
            xp[q / 2]     = packh(XSCALE * (lv.x * pv.x), XSCALE * (lv.y * pv.y));
            xp[q / 2 + 1] = packh(XSCALE * (lv.z * pv.z), XSCALE * (lv.w * pv.w));
        }
        char* xhp = smc + SM_XH0 + bp_ * 80 + bkh * 32;
        *(uint4*)(xhp)      = make_uint4(xp[0], xp[1], xp[2], xp[3]);
        *(uint4*)(xhp + 16) = make_uint4(xp[4], xp[5], xp[6], xp[7]);
        const int wr = tid >> 2;
        const int ws = tid & 3;
        *(uint4*)(smc + SM_WH0 + wr * 80 + ws * 16) = *(const uint4*)(g_W1h + wr * 512 + ws * 8);
    }
    __syncthreads();

    for (int c = 0; c < 16; c++) {
        const int s = c & 1;
        if (c + 1 < 16) {
            const int cn = c + 1;
            const int sn = cn & 1;
            const bool mul = (cn < 8);
            const int kb = (mul ? cn * 32 : (cn - 8) * 32) + bkh * 16;
            uint32_t xp[8];
#pragma unroll
            for (int q = 0; q < 16; q += 4) {
                float4 lv = *(const float4*)(blrow + kb + q);
                float4 pv = *(const float4*)(bprow + kb + q);
                float x0, x1, x2, x3;
                if (mul) {
                    x0 = XSCALE * (lv.x * pv.x); x1 = XSCALE * (lv.y * pv.y);
                    x2 = XSCALE * (lv.z * pv.z); x3 = XSCALE * (lv.w * pv.w);
                } else {
                    x0 = XSCALE * fabsf(lv.x - pv.x); x1 = XSCALE * fabsf(lv.y - pv.y);
                    x2 = XSCALE * fabsf(lv.z - pv.z); x3 = XSCALE * fabsf(lv.w - pv.w);
                }
                xp[q / 2]     = packh(x0, x1);
                xp[q / 2 + 1] = packh(x2, x3);
            }
            char* xhp = smc + xhOff[sn] + bp_ * 80 + bkh * 32;
            *(uint4*)(xhp)      = make_uint4(xp[0], xp[1], xp[2], xp[3]);
            *(uint4*)(xhp + 16) = make_uint4(xp[4], xp[5], xp[6], xp[7]);
            const int wr = tid >> 2;
            const int ws = tid & 3;
            *(uint4*)(smc + whOff[sn] + wr * 80 + ws * 16) =
                *(const uint4*)(g_W1h + wr * 512 + cn * 32 + ws * 8);
        }
#pragma unroll
        for (int ks = 0; ks < 2; ks++) {
            uint32_t ah[4][4];
#pragma unroll
            for (int mt = 0; mt < 4; mt++) {
                uint32_t rowa = (uint32_t)(mw * 64 + mt * 16) + a_row;
                ldsm_x4(ah[mt], sbase + xhOff[s] + rowa * 80 + ks * 32 + a_colh);
            }
#pragma unroll
            for (int nt = 0; nt < 4; nt++) {
                uint32_t rowb = (uint32_t)(nw * 32 + nt * 8) + b_row;
                uint32_t bh[2];
                ldsm_x2(bh, sbase + whOff[s] + rowb * 80 + ks * 32 + b_colh);
#pragma unroll
                for (int mt = 0; mt < 4; mt++)
                    mma_f16(acc[mt][nt], ah[mt], bh[0], bh[1]);
            }
        }
        __syncthreads();
    }

    // ---------- epilogue 1a: z1 = acc/32 + A1 + B1, gelu ----------
#pragma unroll
    for (int mt = 0; mt < 4; mt++) {
#pragma unroll
        for (int rh = 0; rh < 2; rh++) {
            int row = mw * 64 + mt * 16 + (lane >> 2) + rh * 8;
            int il = row >> 4, jl = row & 15;
#pragma unroll
            for (int nt = 0; nt < 4; nt++) {
                int colb = nw * 32 + nt * 8 + (lane & 3) * 2;
                float2 a1v = *(const float2*)&A1s[il * 132 + colb];
                float2 b1v = *(const float2*)&B1s[jl * 132 + colb];
                acc[mt][nt][rh * 2 + 0] = gelu_f(acc[mt][nt][rh * 2 + 0] * XINV + a1v.x + b1v.x);
                acc[mt][nt][rh * 2 + 1] = gelu_f(acc[mt][nt][rh * 2 + 1] * XINV + a1v.y + b1v.y);
            }
        }
    }
    __syncthreads();   // phase-1 smem dead; Y region safe

    // ---------- epilogue 1b: Y*32 fp16 to smem chunk nw ----------
#pragma unroll
    for (int mt = 0; mt < 4; mt++) {
#pragma unroll
        for (int nt = 0; nt < 4; nt++) {
#pragma unroll
            for (int rh = 0; rh < 2; rh++) {
                int row = mw * 64 + mt * 16 + (lane >> 2) + rh * 8;
                int cloc = nt * 8 + (lane & 3) * 2;
                uint32_t hp = packh(XSCALE * acc[mt][nt][rh * 2 + 0],
                                    XSCALE * acc[mt][nt][rh * 2 + 1]);
                *(uint32_t*)(smc + SM_YH(nw) + row * 80 + cloc * 2) = hp;
            }
        }
    }
#pragma unroll
    for (int mt = 0; mt < 4; mt++)
#pragma unroll
        for (int nt = 0; nt < 4; nt++)
#pragma unroll
            for (int r = 0; r < 4; r++) acc[mt][nt][r] = 0.0f;
    __syncthreads();

    // ---------- GEMM2: K=128 in 4 chunks of 32 ----------
    for (int kc = 0; kc < 4; kc++) {
        {
            const int wr = tid >> 2;
            const int ws = tid & 3;
            *(uint4*)(smc + SM_W2H + wr * 80 + ws * 16) =
                *(const uint4*)(g_W2h + wr * 128 + kc * 32 + ws * 8);
        }
        __syncthreads();
#pragma unroll
        for (int ks = 0; ks < 2; ks++) {
            uint32_t ah[4][4];
#pragma unroll
            for (int mt = 0; mt < 4; mt++) {
                uint32_t rowa = (uint32_t)(mw * 64 + mt * 16) + a_row;
                ldsm_x4(ah[mt], sbase + SM_YH(kc) + rowa * 80 + ks * 32 + a_colh);
            }
#pragma unroll
            for (int nt = 0; nt < 4; nt++) {
                uint32_t rowb = (uint32_t)(nw * 32 + nt * 8) + b_row;
                uint32_t bh[2];
                ldsm_x2(bh, sbase + SM_W2H + rowb * 80 + ks * 32 + b_colh);
#pragma unroll
                for (int mt = 0; mt < 4; mt++)
                    mma_f16(acc[mt][nt], ah[mt], bh[0], bh[1]);
            }
        }
        __syncthreads();
    }

    // ---------- epilogue 2: gelu + w3 dot, reduce, outputs ----------
    {
        float part[4][2];
#pragma unroll
        for (int mt = 0; mt < 4; mt++) { part[mt][0] = 0.0f; part[mt][1] = 0.0f; }
#pragma unroll
        for (int nt = 0; nt < 4; nt++) {
            int colb = nw * 32 + nt * 8 + (lane & 3) * 2;
            float w3a = __ldg(W3 + colb), w3b = __ldg(W3 + colb + 1);
            float b2a = __ldg(b2g + colb), b2b = __ldg(b2g + colb + 1);
#pragma unroll
            for (int mt = 0; mt < 4; mt++) {
                part[mt][0] += w3a * gelu_f(acc[mt][nt][0] * XINV + b2a) + w3b * gelu_f(acc[mt][nt][1] * XINV + b2b);
                part[mt][1] += w3a * gelu_f(acc[mt][nt][2] * XINV + b2a) + w3b * gelu_f(acc[mt][nt][3] * XINV + b2b);
            }
        }
#pragma unroll
        for (int off = 1; off <= 2; off <<= 1) {
#pragma unroll
            for (int mt = 0; mt < 4; mt++) {
                part[mt][0] += __shfl_xor_sync(0xFFFFFFFFu, part[mt][0], off);
                part[mt][1] += __shfl_xor_sync(0xFFFFFFFFu, part[mt][1], off);
            }
        }
        if ((lane & 3) == 0) {
            float* ZP = (float*)(smc + SM_ZP);
#pragma unroll
            for (int mt = 0; mt < 4; mt++) {
                int row0 = mw * 64 + mt * 16 + (lane >> 2);
                ZP[nw * 256 + row0]     = part[mt][0];
                ZP[nw * 256 + row0 + 8] = part[mt][1];
            }
        }
    }
    __syncthreads();
    if (tid < 256) {
        const float* ZP = (const float*)(smc + SM_ZP);
        float v = ZP[tid] + ZP[256 + tid] + ZP[512 + tid] + ZP[768 + tid] + b3[0];
        if (isnan(v)) v = 0.0f;
        else if (isinf(v)) v = (v > 0.0f) ? 20.0f : -20.0f;
        const int gi = it + (tid >> 4);
        const int gj = jt + (tid & 15);
        if (g_lmask[b * 256 + gi] || g_pmask[b * 256 + gj]) v = -20.0f;
        const int idx = 4 + (b * 65536 + gi * 256 + gj);
        out[idx] = v;
        out[idx + 262144] = 1.0f / (1.0f + expf(-v));
    }
}

// -------------------- top-k (R5, proven) --------------------
__device__ __forceinline__ int wredsum_i(int v) {
#pragma unroll
    for (int o = 16; o; o >>= 1) v += __shfl_xor_sync(0xFFFFFFFFu, v, o);
    return v;
}
__device__ __forceinline__ float wredsum_f(float v) {
#pragma unroll
    for (int o = 16; o; o >>= 1) v += __shfl_xor_sync(0xFFFFFFFFu, v, o);
    return v;
}

__global__ __launch_bounds__(1024) void topk_kernel(float* out) {
    const int b = blockIdx.x;
    const float* data = out + 4 + b * NPAIR_B;
    const int tid = threadIdx.x, lane = tid & 31, wid = tid >> 5;
    __shared__ int hist[256];
    __shared__ unsigned s_pref;
    __shared__ int s_above;
    __shared__ float sf[32], sf2[32];
    __shared__ int si[32];

    unsigned prefix = 0u;
    int above = 0;
    for (int pass = 0; pass < 4; pass++) {
        const int bpos = 24 - 8 * pass;
        if (tid < 256) hist[tid] = 0;
        __syncthreads();
        const unsigned maskHi = (pass == 0) ? 0u : (0xFFFFFFFFu << (bpos + 8));
        for (int i = tid; i < NPAIR_B; i += 1024) {
            unsigned u = __float_as_uint(data[i]);
            unsigned k = (u & 0x80000000u) ? ~u : (u | 0x80000000u);
            if (((k ^ prefix) & maskHi) == 0)
                atomicAdd(&hist[(k >> bpos) & 255], 1);
        }
        __syncthreads();
        if (tid == 0) {
            int run = 0, chosen = 0, abv = above;
            for (int x = 255; x >= 0; --x) {
                int nr = run + hist[x];
                if (above + nr >= TOPK_K) { chosen = x; abv = above + run; break; }
                run = nr;
            }
            s_pref = prefix | ((unsigned)chosen << bpos);
            s_above = abv;
        }
        __syncthreads();
        prefix = s_pref;
        above = s_above;
        __syncthreads();
    }

    unsigned ut = (prefix & 0x80000000u) ? (prefix & 0x7FFFFFFFu) : ~prefix;
    const float vT = __uint_as_float(ut);

    float s1 = 0.0f, s2 = 0.0f;
    int cg = 0;
    for (int i = tid; i < NPAIR_B; i += 1024) {
        float v = data[i];
        unsigned u = __float_as_uint(v);
        unsigned k = (u & 0x80000000u) ? ~u : (u | 0x80000000u);
        if (k > prefix) {
            float e = expf(v - vT);
            s1 += e; s2 += e * v; cg++;
        }
    }
    s1 = wredsum_f(s1);
    s2 = wredsum_f(s2);
    cg = wredsum_i(cg);
    if (lane == 0) { sf[wid] = s1; sf2[wid] = s2; si[wid] = cg; }
    __syncthreads();
    if (tid == 0) {
        float S1 = 0.0f, S2 = 0.0f;
        int CG = 0;
        for (int w = 0; w < 32; w++) { S1 += sf[w]; S2 += sf2[w]; CG += si[w]; }
        int r = TOPK_K - CG;
        S1 += (float)r;
        S2 += (float)r * vT;
        out[b] = S2 / S1;
    }
}

// ---------------------------------------------------------------------------
extern "C" void kernel_launch(void* const* d_in, const int* in_sizes, int n_in,
                              void* d_out, int out_size)
{
    const float* ltok = (const float*)d_in[0];
    const float* ptok = (const float*)d_in[1];
    const void*  lpad = d_in[2];
    const void*  ppad = d_in[3];
    const float* Wl = (const float*)d_in[4];
    const float* bl = (const float*)d_in[5];
    const float* Wp = (const float*)d_in[6];
    const float* bp = (const float*)d_in[7];
    const float* W1 = (const float*)d_in[8];
    const float* b1 = (const float*)d_in[9];
    const float* W2 = (const float*)d_in[10];
    const float* b2 = (const float*)d_in[11];
    const float* W3 = (const float*)d_in[12];
    const float* b3 = (const float*)d_in[13];
    float* out = (float*)d_out;

    detect_kernel<<<2, 256>>>((const unsigned char*)lpad, (const unsigned char*)ppad);
    mask_kernel<<<2, 1024>>>(lpad, ppad);
    wprep_kernel<<<320, 256>>>(W1, W2);
    proj_kernel<<<dim3(4, 32), 256>>>(ltok, ptok, Wl, bl, Wp, bp);
    a1b1_kernel<<<dim3(2, 32), 256>>>(W1, b1);

    cudaFuncSetAttribute(pair_kernel, cudaFuncAttributeMaxDynamicSharedMemorySize, SMEM_PAIR);
    pair_kernel<<<dim3(16, 16, 4), 512, SMEM_PAIR>>>(b2, W3, b3, out);

    topk_kernel<<<4, 1024>>>(out);
}

// round 9
// speedup vs baseline: 9.2481x; 1.0628x over previous
#include <cuda_runtime.h>
#include <cuda_fp16.h>
#include <cstdint>
#include <math.h>

// ---------------------------------------------------------------------------
// PairwiseInteractionHead B=4, L=256, D=256, H=128, TOPK=100.
// Round 8: fp16 1-pass mma.sync + half2 X-build (no fp32 in the build path)
// + K=64 chunks (half the barriers).
// X_mul = fp16(32l) * fp16(p); X_abs = |fp16(32l) - fp16(32p)|  (scale 32,
// unscaled exactly by 1/32 in epilogue). W fp16. rel_err budget ~2e-4.
// ---------------------------------------------------------------------------

#define NB 4
#define NPAIR_B 65536
#define TOPK_K 100
#define XSCALE 32.0f
#define XINV   0.03125f

__device__ float g_lproj[NB * 256 * 256];
__device__ float g_pproj[NB * 256 * 256];
__device__ float g_A1[NB * 256 * 128];
__device__ float g_B1[NB * 256 * 128];
__device__ int   g_lmask[NB * 256];
__device__ int   g_pmask[NB * 256];
__device__ int   g_flags[2];
__device__ __half g_W1h[128 * 512];
__device__ __half g_W2h[128 * 128];

__device__ __forceinline__ float gelu_f(float x) {
    return 0.5f * x * (1.0f + erff(x * 0.70710678118654752440f));
}

// -------------------- low-level helpers --------------------
__device__ __forceinline__ uint32_t smem_u32(const void* p) {
    uint32_t a;
    asm("{ .reg .u64 t; cvta.to.shared.u64 t, %1; cvt.u32.u64 %0, t; }" : "=r"(a) : "l"(p));
    return a;
}
__device__ __forceinline__ uint32_t packh(float x0, float x1) {
    uint32_t d;
    asm("cvt.rn.f16x2.f32 %0, %1, %2;" : "=r"(d) : "f"(x1), "f"(x0));
    return d;
}
__device__ __forceinline__ uint32_t hmul2u(uint32_t a, uint32_t b) {
    __half2 r = __hmul2(*(__half2*)&a, *(__half2*)&b);
    return *(uint32_t*)&r;
}
__device__ __forceinline__ uint32_t habsdiff2u(uint32_t a, uint32_t b) {
    __half2 r = __habs2(__hsub2(*(__half2*)&a, *(__half2*)&b));
    return *(uint32_t*)&r;
}
__device__ __forceinline__ void ldsm_x4(uint32_t* r, uint32_t addr) {
    asm volatile("ldmatrix.sync.aligned.m8n8.x4.shared.b16 {%0,%1,%2,%3}, [%4];"
        : "=r"(r[0]), "=r"(r[1]), "=r"(r[2]), "=r"(r[3]) : "r"(addr));
}
__device__ __forceinline__ void ldsm_x2(uint32_t* r, uint32_t addr) {
    asm volatile("ldmatrix.sync.aligned.m8n8.x2.shared.b16 {%0,%1}, [%2];"
        : "=r"(r[0]), "=r"(r[1]) : "r"(addr));
}
__device__ __forceinline__ void mma_f16(float* c, const uint32_t* a, uint32_t b0, uint32_t b1) {
    asm volatile(
        "mma.sync.aligned.m16n8k16.row.col.f32.f16.f16.f32 "
        "{%0,%1,%2,%3}, {%4,%5,%6,%7}, {%8,%9}, {%0,%1,%2,%3};"
        : "+f"(c[0]), "+f"(c[1]), "+f"(c[2]), "+f"(c[3])
        : "r"(a[0]), "r"(a[1]), "r"(a[2]), "r"(a[3]), "r"(b0), "r"(b1));
}

// -------------------- pad-dtype detection + masks (proven) --------------------
__global__ void detect_kernel(const unsigned char* lp, const unsigned char* pp) {
    __shared__ int s_nonbin, s_oddnz, s_anynz;
    const unsigned char* p = blockIdx.x ? pp : lp;
    if (threadIdx.x == 0) { s_nonbin = 0; s_oddnz = 0; s_anynz = 0; }
    __syncthreads();
    int nonbin = 0, oddnz = 0, anynz = 0;
    for (int i = threadIdx.x; i < 1024; i += blockDim.x) {
        unsigned v = p[i];
        if (v) { anynz = 1; if (v > 1u) nonbin = 1; if (i & 3) oddnz = 1; }
    }
    if (nonbin) atomicOr(&s_nonbin, 1);
    if (oddnz)  atomicOr(&s_oddnz, 1);
    if (anynz)  atomicOr(&s_anynz, 1);
    __syncthreads();
    if (threadIdx.x == 0) {
        int f;
        if (!s_anynz) f = 0;
        else if (s_nonbin) f = 2;
        else if (s_oddnz) f = 1;
        else f = 3;
        g_flags[blockIdx.x] = f;
    }
}

__global__ void mask_kernel(const void* lp, const void* pp) {
    int buf = blockIdx.x;
    const void* p = buf ? pp : lp;
    int f = g_flags[buf];
    int i = threadIdx.x;
    int m;
    if (f == 0) m = 0;
    else if (f == 1) m = (((const unsigned char*)p)[i] != 0);
    else if (f == 2) m = (((const float*)p)[i] != 0.0f);
    else m = (((const int*)p)[i] != 0);
    (buf ? g_pmask : g_lmask)[i] = m;
}

// -------------------- weight fp16 prep --------------------
__global__ void wprep_kernel(const float* __restrict__ W1, const float* __restrict__ W2) {
    int i = blockIdx.x * 256 + threadIdx.x;
    if (i < 128 * 512) {
        g_W1h[i] = __float2half_rn(W1[(i >> 9) * 1024 + 512 + (i & 511)]);
    } else {
        int j = i - 128 * 512;
        if (j < 128 * 128) g_W2h[j] = __float2half_rn(W2[j]);
    }
}

// -------------------- projection GEMM (R1, proven) --------------------
__global__ __launch_bounds__(256) void proj_kernel(
    const float* __restrict__ ltok, const float* __restrict__ ptok,
    const float* __restrict__ Wl, const float* __restrict__ bl,
    const float* __restrict__ Wp, const float* __restrict__ bp)
{
    __shared__ float As[16][68];
    __shared__ float Bs[16][68];
    const int n0 = blockIdx.x * 64;
    const int m0 = blockIdx.y * 64;
    const bool isP = (m0 >= 1024);
    const float* in   = isP ? ptok : ltok;
    const float* W    = isP ? Wp : Wl;
    const float* bias = isP ? bp : bl;
    const int mb = isP ? (m0 - 1024) : m0;
    float* outp = isP ? g_pproj : g_lproj;
    const int tid = threadIdx.x;
    const int tx = tid & 15, ty = tid >> 4;
    const int lr = tid >> 2, lc = (tid & 3) * 4;
    float acc[4][4] = {};
    for (int kt = 0; kt < 256; kt += 16) {
        float4 a4 = *(const float4*)&in[(mb + lr) * 256 + kt + lc];
        float4 b4 = *(const float4*)&W[(n0 + lr) * 256 + kt + lc];
        As[lc + 0][lr] = a4.x; As[lc + 1][lr] = a4.y; As[lc + 2][lr] = a4.z; As[lc + 3][lr] = a4.w;
        Bs[lc + 0][lr] = b4.x; Bs[lc + 1][lr] = b4.y; Bs[lc + 2][lr] = b4.z; Bs[lc + 3][lr] = b4.w;
        __syncthreads();
#pragma unroll
        for (int e = 0; e < 16; e++) {
            float4 av = *(const float4*)&As[e][ty * 4];
            float4 bv = *(const float4*)&Bs[e][tx * 4];
            acc[0][0] += av.x * bv.x; acc[0][1] += av.x * bv.y; acc[0][2] += av.x * bv.z; acc[0][3] += av.x * bv.w;
            acc[1][0] += av.y * bv.x; acc[1][1] += av.y * bv.y; acc[1][2] += av.y * bv.z; acc[1][3] += av.y * bv.w;
            acc[2][0] += av.z * bv.x; acc[2][1] += av.z * bv.y; acc[2][2] += av.z * bv.z; acc[2][3] += av.z * bv.w;
            acc[3][0] += av.w * bv.x; acc[3][1] += av.w * bv.y; acc[3][2] += av.w * bv.z; acc[3][3] += av.w * bv.w;
        }
        __syncthreads();
    }
#pragma unroll
    for (int ii = 0; ii < 4; ii++)
#pragma unroll
        for (int jj = 0; jj < 4; jj++) {
            int n = n0 + tx * 4 + jj;
            outp[(mb + ty * 4 + ii) * 256 + n] = acc[ii][jj] + bias[n];
        }
}

// -------------------- A1/B1 GEMM (R1, proven) --------------------
__global__ __launch_bounds__(256) void a1b1_kernel(
    const float* __restrict__ W1, const float* __restrict__ b1)
{
    __shared__ float As[16][68];
    __shared__ float Bs[16][68];
    const int n0 = blockIdx.x * 64;
    const int m0 = blockIdx.y * 64;
    const bool isP = (m0 >= 1024);
    const float* in = isP ? g_pproj : g_lproj;
    const int mb = isP ? (m0 - 1024) : m0;
    const int colOff = isP ? 256 : 0;
    float* outp = isP ? g_B1 : g_A1;
    const int tid = threadIdx.x;
    const int tx = tid & 15, ty = tid >> 4;
    const int lr = tid >> 2, lc = (tid & 3) * 4;
    float acc[4][4] = {};
    for (int kt = 0; kt < 256; kt += 16) {
        float4 a4 = *(const float4*)&in[(mb + lr) * 256 + kt + lc];
        float4 b4 = *(const float4*)&W1[(n0 + lr) * 1024 + colOff + kt + lc];
        As[lc + 0][lr] = a4.x; As[lc + 1][lr] = a4.y; As[lc + 2][lr] = a4.z; As[lc + 3][lr] = a4.w;
        Bs[lc + 0][lr] = b4.x; Bs[lc + 1][lr] = b4.y; Bs[lc + 2][lr] = b4.z; Bs[lc + 3][lr] = b4.w;
        __syncthreads();
#pragma unroll
        for (int e = 0; e < 16; e++) {
            float4 av = *(const float4*)&As[e][ty * 4];
            float4 bv = *(const float4*)&Bs[e][tx * 4];
            acc[0][0] += av.x * bv.x; acc[0][1] += av.x * bv.y; acc[0][2] += av.x * bv.z; acc[0][3] += av.x * bv.w;
            acc[1][0] += av.y * bv.x; acc[1][1] += av.y * bv.y; acc[1][2] += av.y * bv.z; acc[1][3] += av.y * bv.w;
            acc[2][0] += av.z * bv.x; acc[2][1] += av.z * bv.y; acc[2][2] += av.z * bv.z; acc[2][3] += av.z * bv.w;
            acc[3][0] += av.w * bv.x; acc[3][1] += av.w * bv.y; acc[3][2] += av.w * bv.z; acc[3][3] += av.w * bv.w;
        }
        __syncthreads();
    }
#pragma unroll
    for (int ii = 0; ii < 4; ii++)
#pragma unroll
        for (int jj = 0; jj < 4; jj++) {
            int n = n0 + tx * 4 + jj;
            float bv = isP ? 0.0f : b1[n];
            outp[(mb + ty * 4 + ii) * 128 + n] = acc[ii][jj] + bv;
        }
}

// -------------------- tensor-core pair kernel (fp16, half2 build, K=64) -----
// 512 threads = 16 warps, 4(m)x4(n); warp tile 64 pairs x 32 h.
// phase-1 smem byte offsets:
#define SM_LH32  0u        // [16][264] half (32*l)  = 8448
#define SM_PH    8448u     // [16][264] half (p)
#define SM_PH32  16896u    // [16][264] half (32*p)  -> 25344
#define SM_X0    25344u    // [256][144B] fp16 X chunk (64 k)
#define SM_X1    62208u
#define SM_W0    99072u    // [128][144B]
#define SM_W1B   117504u
#define SM_A1    135936u   // [16][132] f32
#define SM_B1    144384u   // -> 152832
// phase-2 aliases (phase-1 dead first):
#define SM_YH(c)  ((c) * 20480u)   // 4 chunks [256][80B] -> 81920
#define SM_W2H    81920u           // [128][80B] -> 92160
#define SM_ZP     92160u           // [4][256] f32 -> 96256
#define SMEM_PAIR 152832

__global__ __launch_bounds__(512, 1) void pair_kernel(
    const float* __restrict__ b2g, const float* __restrict__ W3,
    const float* __restrict__ b3, float* __restrict__ out)
{
    extern __shared__ char smc[];
    float* A1s = (float*)(smc + SM_A1);
    float* B1s = (float*)(smc + SM_B1);
    const uint32_t sbase = smem_u32(smc);

    const int tid  = threadIdx.x;
    const int lane = tid & 31;
    const int wid  = tid >> 5;
    const int mw   = wid & 3;
    const int nw   = wid >> 2;
    const int b  = blockIdx.z;
    const int it = blockIdx.y * 16;
    const int jt = blockIdx.x * 16;

    const uint32_t xOff[2] = {SM_X0, SM_X1};
    const uint32_t wOff[2] = {SM_W0, SM_W1B};

    const uint32_t a_row  = (lane & 7) + ((lane >> 3) & 1) * 8;
    const uint32_t a_colh = ((lane >> 4) & 1) * 16;
    const uint32_t b_row  = lane & 7;
    const uint32_t b_colh = ((lane >> 3) & 1) * 16;

    // ---- prologue: convert L/P tiles to fp16 (scaled) + load A1/B1 ----
    {
        const float* lsrc = g_lproj + (size_t)(b * 256 + it) * 256;
        const float* psrc = g_pproj + (size_t)(b * 256 + jt) * 256;
        int r = tid >> 5;
        int c = (tid & 31) * 8;
        const float* lr_ = lsrc + r * 256 + c;
        const float* pr_ = psrc + r * 256 + c;
        float4 l0 = *(const float4*)lr_;
        float4 l1 = *(const float4*)(lr_ + 4);
        float4 p0 = *(const float4*)pr_;
        float4 p1 = *(const float4*)(pr_ + 4);
        uint4 lh;
        lh.x = packh(XSCALE * l0.x, XSCALE * l0.y);
        lh.y = packh(XSCALE * l0.z, XSCALE * l0.w);
        lh.z = packh(XSCALE * l1.x, XSCALE * l1.y);
        lh.w = packh(XSCALE * l1.z, XSCALE * l1.w);
        *(uint4*)(smc + SM_LH32 + r * 528 + c * 2) = lh;
        uint4 ph;
        ph.x = packh(p0.x, p0.y);
        ph.y = packh(p0.z, p0.w);
        ph.z = packh(p1.x, p1.y);
        ph.w = packh(p1.z, p1.w);
        *(uint4*)(smc + SM_PH + r * 528 + c * 2) = ph;
        uint4 ph32;
        ph32.x = packh(XSCALE * p0.x, XSCALE * p0.y);
        ph32.y = packh(XSCALE * p0.z, XSCALE * p0.w);
        ph32.z = packh(XSCALE * p1.x, XSCALE * p1.y);
        ph32.w = packh(XSCALE * p1.z, XSCALE * p1.w);
        *(uint4*)(smc + SM_PH32 + r * 528 + c * 2) = ph32;

        const float* a1src = g_A1 + (size_t)(b * 256 + it) * 128;
        const float* b1src = g_B1 + (size_t)(b * 256 + jt) * 128;
        int rc = (tid & 31) * 4;
        *(float4*)&A1s[r * 132 + rc] = *(const float4*)&a1src[r * 128 + rc];
        *(float4*)&B1s[r * 132 + rc] = *(const float4*)&b1src[r * 128 + rc];
    }

    float acc[4][4][4];
#pragma unroll
    for (int mt = 0; mt < 4; mt++)
#pragma unroll
        for (int nt = 0; nt < 4; nt++)
#pragma unroll
            for (int r = 0; r < 4; r++) acc[mt][nt][r] = 0.0f;

    // build mapping: pair bp_, k-half bkh (32 k each)
    const int bp_ = tid & 255;
    const int bkh = tid >> 8;
    const char* lbase  = smc + SM_LH32 + (bp_ >> 4) * 528;
    const char* pbase  = smc + SM_PH   + (bp_ & 15) * 528;
    const char* p32base = smc + SM_PH32 + (bp_ & 15) * 528;

    __syncthreads();

    // ---------- GEMM1: 8 K-chunks of 64 ----------
    // build chunk into buffer
#define BUILD_CHUNK(cn, sn) do { \
        const bool mul_ = ((cn) < 4); \
        const int kb_ = ((cn) & 3) * 64 + bkh * 32; \
        const uint4* ls_ = (const uint4*)(lbase + kb_ * 2); \
        const uint4* ps_ = (const uint4*)((mul_ ? pbase : p32base) + kb_ * 2); \
        char* dst_ = smc + xOff[sn] + bp_ * 144 + bkh * 64; \
        _Pragma("unroll") \
        for (int q_ = 0; q_ < 4; q_++) { \
            uint4 lv_ = ls_[q_]; \
            uint4 pv_ = ps_[q_]; \
            uint4 ov_; \
            if (mul_) { \
                ov_.x = hmul2u(lv_.x, pv_.x); ov_.y = hmul2u(lv_.y, pv_.y); \
                ov_.z = hmul2u(lv_.z, pv_.z); ov_.w = hmul2u(lv_.w, pv_.w); \
            } else { \
                ov_.x = habsdiff2u(lv_.x, pv_.x); ov_.y = habsdiff2u(lv_.y, pv_.y); \
                ov_.z = habsdiff2u(lv_.z, pv_.z); ov_.w = habsdiff2u(lv_.w, pv_.w); \
            } \
            *(uint4*)(dst_ + q_ * 16) = ov_; \
        } \
        const int wr_ = tid >> 2; \
        const int ws_ = tid & 3; \
        const uint4* wsrc_ = (const uint4*)(g_W1h + wr_ * 512 + (cn) * 64 + ws_ * 16); \
        char* wdst_ = smc + wOff[sn] + wr_ * 144 + ws_ * 32; \
        *(uint4*)(wdst_)      = wsrc_[0]; \
        *(uint4*)(wdst_ + 16) = wsrc_[1]; \
    } while (0)

    BUILD_CHUNK(0, 0);
    __syncthreads();

    for (int c = 0; c < 8; c++) {
        const int s = c & 1;
        if (c + 1 < 8) BUILD_CHUNK(c + 1, (c + 1) & 1);
#pragma unroll
        for (int ks = 0; ks < 4; ks++) {
            uint32_t ah[4][4];
#pragma unroll
            for (int mt = 0; mt < 4; mt++) {
                uint32_t rowa = (uint32_t)(mw * 64 + mt * 16) + a_row;
                ldsm_x4(ah[mt], sbase + xOff[s] + rowa * 144 + ks * 32 + a_colh);
            }
#pragma unroll
            for (int nt = 0; nt < 4; nt++) {
                uint32_t rowb = (uint32_t)(nw * 32 + nt * 8) + b_row;
                uint32_t bh[2];
                ldsm_x2(bh, sbase + wOff[s] + rowb * 144 + ks * 32 + b_colh);
#pragma unroll
                for (int mt = 0; mt < 4; mt++)
                    mma_f16(acc[mt][nt], ah[mt], bh[0], bh[1]);
            }
        }
        __syncthreads();
    }
#undef BUILD_CHUNK

    // ---------- epilogue 1a: z1 = acc/32 + A1 + B1, gelu ----------
#pragma unroll
    for (int mt = 0; mt < 4; mt++) {
#pragma unroll
        for (int rh = 0; rh < 2; rh++) {
            int row = mw * 64 + mt * 16 + (lane >> 2) + rh * 8;
            int il = row >> 4, jl = row & 15;
#pragma unroll
            for (int nt = 0; nt < 4; nt++) {
                int colb = nw * 32 + nt * 8 + (lane & 3) * 2;
                float2 a1v = *(const float2*)&A1s[il * 132 + colb];
                float2 b1v = *(const float2*)&B1s[jl * 132 + colb];
                acc[mt][nt][rh * 2 + 0] = gelu_f(acc[mt][nt][rh * 2 + 0] * XINV + a1v.x + b1v.x);
                acc[mt][nt][rh * 2 + 1] = gelu_f(acc[mt][nt][rh * 2 + 1] * XINV + a1v.y + b1v.y);
            }
        }
    }
    __syncthreads();   // phase-1 smem dead; Y region safe

    // ---------- epilogue 1b: Y*32 fp16 to smem chunk nw ----------
#pragma unroll
    for (int mt = 0; mt < 4; mt++) {
#pragma unroll
        for (int nt = 0; nt < 4; nt++) {
#pragma unroll
            for (int rh = 0; rh < 2; rh++) {
                int row = mw * 64 + mt * 16 + (lane >> 2) + rh * 8;
                int cloc = nt * 8 + (lane & 3) * 2;
                uint32_t hp = packh(XSCALE * acc[mt][nt][rh * 2 + 0],
                                    XSCALE * acc[mt][nt][rh * 2 + 1]);
                *(uint32_t*)(smc + SM_YH(nw) + row * 80 + cloc * 2) = hp;
            }
        }
    }
#pragma unroll
    for (int mt = 0; mt < 4; mt++)
#pragma unroll
        for (int nt = 0; nt < 4; nt++)
#pragma unroll
            for (int r = 0; r < 4; r++) acc[mt][nt][r] = 0.0f;
    __syncthreads();

    // ---------- GEMM2: K=128 in 4 chunks of 32 ----------
    for (int kc = 0; kc < 4; kc++) {
        {
            const int wr = tid >> 2;
            const int ws = tid & 3;
            *(uint4*)(smc + SM_W2H + wr * 80 + ws * 16) =
                *(const uint4*)(g_W2h + wr * 128 + kc * 32 + ws * 8);
        }
        __syncthreads();
#pragma unroll
        for (int ks = 0; ks < 2; ks++) {
            uint32_t ah[4][4];
#pragma unroll
            for (int mt = 0; mt < 4; mt++) {
                uint32_t rowa = (uint32_t)(mw * 64 + mt * 16) + a_row;
                ldsm_x4(ah[mt], sbase + SM_YH(kc) + rowa * 80 + ks * 32 + a_colh);
            }
#pragma unroll
            for (int nt = 0; nt < 4; nt++) {
                uint32_t rowb = (uint32_t)(nw * 32 + nt * 8) + b_row;
                uint32_t bh[2];
                ldsm_x2(bh, sbase + SM_W2H + rowb * 80 + ks * 32 + b_colh);
#pragma unroll
                for (int mt = 0; mt < 4; mt++)
                    mma_f16(acc[mt][nt], ah[mt], bh[0], bh[1]);
            }
        }
        __syncthreads();
    }

    // ---------- epilogue 2: gelu + w3 dot, reduce, outputs ----------
    {
        float part[4][2];
#pragma unroll
        for (int mt = 0; mt < 4; mt++) { part[mt][0] = 0.0f; part[mt][1] = 0.0f; }
#pragma unroll
        for (int nt = 0; nt < 4; nt++) {
            int colb = nw * 32 + nt * 8 + (lane & 3) * 2;
            float w3a = __ldg(W3 + colb), w3b = __ldg(W3 + colb + 1);
            float b2a = __ldg(b2g + colb), b2b = __ldg(b2g + colb + 1);
#pragma unroll
            for (int mt = 0; mt < 4; mt++) {
                part[mt][0] += w3a * gelu_f(acc[mt][nt][0] * XINV + b2a) + w3b * gelu_f(acc[mt][nt][1] * XINV + b2b);
                part[mt][1] += w3a * gelu_f(acc[mt][nt][2] * XINV + b2a) + w3b * gelu_f(acc[mt][nt][3] * XINV + b2b);
            }
        }
#pragma unroll
        for (int off = 1; off <= 2; off <<= 1) {
#pragma unroll
            for (int mt = 0; mt < 4; mt++) {
                part[mt][0] += __shfl_xor_sync(0xFFFFFFFFu, part[mt][0], off);
                part[mt][1] += __shfl_xor_sync(0xFFFFFFFFu, part[mt][1], off);
            }
        }
        if ((lane & 3) == 0) {
            float* ZP = (float*)(smc + SM_ZP);
#pragma unroll
            for (int mt = 0; mt < 4; mt++) {
                int row0 = mw * 64 + mt * 16 + (lane >> 2);
                ZP[nw * 256 + row0]     = part[mt][0];
                ZP[nw * 256 + row0 + 8] = part[mt][1];
            }
        }
    }
    __syncthreads();
    if (tid < 256) {
        const float* ZP = (const float*)(smc + SM_ZP);
        float v = ZP[tid] + ZP[256 + tid] + ZP[512 + tid] + ZP[768 + tid] + b3[0];
        if (isnan(v)) v = 0.0f;
        else if (isinf(v)) v = (v > 0.0f) ? 20.0f : -20.0f;
        const int gi = it + (tid >> 4);
        const int gj = jt + (tid & 15);
        if (g_lmask[b * 256 + gi] || g_pmask[b * 256 + gj]) v = -20.0f;
        const int idx = 4 + (b * 65536 + gi * 256 + gj);
        out[idx] = v;
        out[idx + 262144] = 1.0f / (1.0f + expf(-v));
    }
}

// -------------------- top-k (R5, proven) --------------------
__device__ __forceinline__ int wredsum_i(int v) {
#pragma unroll
    for (int o = 16; o; o >>= 1) v += __shfl_xor_sync(0xFFFFFFFFu, v, o);
    return v;
}
__device__ __forceinline__ float wredsum_f(float v) {
#pragma unroll
    for (int o = 16; o; o >>= 1) v += __shfl_xor_sync(0xFFFFFFFFu, v, o);
    return v;
}

__global__ __launch_bounds__(1024) void topk_kernel(float* out) {
    const int b = blockIdx.x;
    const float* data = out + 4 + b * NPAIR_B;
    const int tid = threadIdx.x, lane = tid & 31, wid = tid >> 5;
    __shared__ int hist[256];
    __shared__ unsigned s_pref;
    __shared__ int s_above;
    __shared__ float sf[32], sf2[32];
    __shared__ int si[32];

    unsigned prefix = 0u;
    int above = 0;
    for (int pass = 0; pass < 4; pass++) {
        const int bpos = 24 - 8 * pass;
        if (tid < 256) hist[tid] = 0;
        __syncthreads();
        const unsigned maskHi = (pass == 0) ? 0u : (0xFFFFFFFFu << (bpos + 8));
        for (int i = tid; i < NPAIR_B; i += 1024) {
            unsigned u = __float_as_uint(data[i]);
            unsigned k = (u & 0x80000000u) ? ~u : (u | 0x80000000u);
            if (((k ^ prefix) & maskHi) == 0)
                atomicAdd(&hist[(k >> bpos) & 255], 1);
        }
        __syncthreads();
        if (tid == 0) {
            int run = 0, chosen = 0, abv = above;
            for (int x = 255; x >= 0; --x) {
                int nr = run + hist[x];
                if (above + nr >= TOPK_K) { chosen = x; abv = above + run; break; }
                run = nr;
            }
            s_pref = prefix | ((unsigned)chosen << bpos);
            s_above = abv;
        }
        __syncthreads();
        prefix = s_pref;
        above = s_above;
        __syncthreads();
    }

    unsigned ut = (prefix & 0x80000000u) ? (prefix & 0x7FFFFFFFu) : ~prefix;
    const float vT = __uint_as_float(ut);

    float s1 = 0.0f, s2 = 0.0f;
    int cg = 0;
    for (int i = tid; i < NPAIR_B; i += 1024) {
        float v = data[i];
        unsigned u = __float_as_uint(v);
        unsigned k = (u & 0x80000000u) ? ~u : (u | 0x80000000u);
        if (k > prefix) {
            float e = expf(v - vT);
            s1 += e; s2 += e * v; cg++;
        }
    }
    s1 = wredsum_f(s1);
    s2 = wredsum_f(s2);
    cg = wredsum_i(cg);
    if (lane == 0) { sf[wid] = s1; sf2[wid] = s2; si[wid] = cg; }
    __syncthreads();
    if (tid == 0) {
        float S1 = 0.0f, S2 = 0.0f;
        int CG = 0;
        for (int w = 0; w < 32; w++) { S1 += sf[w]; S2 += sf2[w]; CG += si[w]; }
        int r = TOPK_K - CG;
        S1 += (float)r;
        S2 += (float)r * vT;
        out[b] = S2 / S1;
    }
}

// ---------------------------------------------------------------------------
extern "C" void kernel_launch(void* const* d_in, const int* in_sizes, int n_in,
                              void* d_out, int out_size)
{
    const float* ltok = (const float*)d_in[0];
    const float* ptok = (const float*)d_in[1];
    const void*  lpad = d_in[2];
    const void*  ppad = d_in[3];
    const float* Wl = (const float*)d_in[4];
    const float* bl = (const float*)d_in[5];
    const float* Wp = (const float*)d_in[6];
    const float* bp = (const float*)d_in[7];
    const float* W1 = (const float*)d_in[8];
    const float* b1 = (const float*)d_in[9];
    const float* W2 = (const float*)d_in[10];
    const float* b2 = (const float*)d_in[11];
    const float* W3 = (const float*)d_in[12];
    const float* b3 = (const float*)d_in[13];
    float* out = (float*)d_out;

    detect_kernel<<<2, 256>>>((const unsigned char*)lpad, (const unsigned char*)ppad);
    mask_kernel<<<2, 1024>>>(lpad, ppad);
    wprep_kernel<<<320, 256>>>(W1, W2);
    proj_kernel<<<dim3(4, 32), 256>>>(ltok, ptok, Wl, bl, Wp, bp);
    a1b1_kernel<<<dim3(2, 32), 256>>>(W1, b1);

    cudaFuncSetAttribute(pair_kernel, cudaFuncAttributeMaxDynamicSharedMemorySize, SMEM_PAIR);
    pair_kernel<<<dim3(16, 16, 4), 512, SMEM_PAIR>>>(b2, W3, b3, out);

    topk_kernel<<<4, 1024>>>(out);
}